// round 11
// baseline (speedup 1.0000x reference)
#include <cuda_runtime.h>
#include <cuda_bf16.h>
#include <cuda_fp16.h>
#include <math.h>
#include <cstdint>

#define BATCH 8
#define GN 8192
#define GDIM 512
#define GHEADS 8
#define GM1 768
#define GDINNER 256

// ---------------- scratch ---------------------------------------------------
__device__ __align__(128) __nv_bfloat16 g_WgT_hi[GM1 * GDIM];
__device__ __align__(128) __nv_bfloat16 g_WgT_lo[GM1 * GDIM];
__device__ __align__(128) __nv_bfloat16 g_xT_hi[(long long)BATCH * GN * GDIM];
__device__ __align__(128) __nv_bfloat16 g_xT_lo[(long long)BATCH * GN * GDIM];
__device__ __align__(128) __nv_bfloat16 g_vT_hi[(long long)BATCH * GN * GDINNER];
__device__ __align__(128) __nv_bfloat16 g_vT_lo[(long long)BATCH * GN * GDINNER];
__device__ __align__(128) __nv_bfloat16 g_W2T_hi[BATCH * GDIM * GDINNER];
__device__ __align__(128) __nv_bfloat16 g_W2T_lo[BATCH * GDIM * GDINNER];
__device__ __align__(128) __half g_QK[(long long)BATCH * 512 * GN];   // q,k fp16 (64MB)
__device__ float g_xnp[8 * BATCH * GN];                // partial token norms
__device__ float g_invnorm[BATCH * GN];
__device__ float g_Gpart[8 * BATCH * GHEADS * 32 * 32];
__device__ float g_Npart[8 * BATCH * GHEADS * 64];     // partial q/k channel norms

// ---------------- helpers ---------------------------------------------------
__device__ __forceinline__ uint32_t smem_to_u32(const void* p) {
    uint32_t a;
    asm("{ .reg .u64 t; cvta.to.shared.u64 t, %1; cvt.u32.u64 %0, t; }" : "=r"(a) : "l"(p));
    return a;
}
__device__ __forceinline__ void ldsm4(uint32_t* r, uint32_t addr) {
    asm volatile("ldmatrix.sync.aligned.m8n8.x4.shared.b16 {%0,%1,%2,%3}, [%4];"
                 : "=r"(r[0]), "=r"(r[1]), "=r"(r[2]), "=r"(r[3]) : "r"(addr));
}
__device__ __forceinline__ void mma16816(float* d, const uint32_t* a, const uint32_t* b) {
    asm volatile("mma.sync.aligned.m16n8k16.row.col.f32.bf16.bf16.f32 "
                 "{%0,%1,%2,%3}, {%4,%5,%6,%7}, {%8,%9}, {%0,%1,%2,%3};"
                 : "+f"(d[0]), "+f"(d[1]), "+f"(d[2]), "+f"(d[3])
                 : "r"(a[0]), "r"(a[1]), "r"(a[2]), "r"(a[3]), "r"(b[0]), "r"(b[1]));
}
#define CP_ASYNC16(dst, src) \
    asm volatile("cp.async.cg.shared.global [%0], [%1], 16;" :: "r"(dst), "l"(src))
#define CP_COMMIT() asm volatile("cp.async.commit_group;")
#define CP_WAIT1()  asm volatile("cp.async.wait_group 1;")
#define CP_WAIT0()  asm volatile("cp.async.wait_group 0;")

__device__ __forceinline__ int swz(int row, int ci) {
    return row * 64 + ((ci ^ ((row >> 1) & 3)) << 4);
}

// ---------------- kernel 0: fold gamma*sqrt(dim) into W, split -------------
__global__ void prep_wg_kernel(const float* __restrict__ w_qkv,
                               const float* __restrict__ gamma) {
    int idx = blockIdx.x * 256 + threadIdx.x;   // over 768*512; out [m][d]
    int m = idx >> 9, d = idx & 511;
    float v = w_qkv[d * GM1 + m] * gamma[d] * 22.627416997969522f;
    __nv_bfloat16 h = __float2bfloat16(v);
    g_WgT_hi[idx] = h;
    g_WgT_lo[idx] = __float2bfloat16(v - __bfloat162float(h));
}

// ---------------- transpose + split x, + partial token norms ---------------
__global__ void transpose_split_kernel(const float* __restrict__ src,
                                       __nv_bfloat16* __restrict__ dhi,
                                       __nv_bfloat16* __restrict__ dlo) {
    __shared__ float t[64][65];
    __shared__ float nr[256];
    int n0 = blockIdx.x * 64, d0 = blockIdx.y * 64, b = blockIdx.z;
    int tid = threadIdx.x;
    int c = tid & 63, r4 = tid >> 6;
    const float* sb = src + ((long long)b * GDIM + d0) * GN + n0;
    #pragma unroll
    for (int i = 0; i < 16; i++) {
        int row = r4 + i * 4;
        t[row][c] = sb[(long long)row * GN + c];
    }
    __syncthreads();
    // bf16 hi/lo transpose out
    int d2 = (tid & 31) * 2, rw = tid >> 5;
    __nv_bfloat16* hb = dhi + ((long long)b * GN + n0) * GDIM + d0;
    __nv_bfloat16* lb = dlo + ((long long)b * GN + n0) * GDIM + d0;
    #pragma unroll
    for (int i = 0; i < 8; i++) {
        int nrow = rw + i * 8;
        float v0 = t[d2][nrow], v1 = t[d2 + 1][nrow];
        __nv_bfloat16 h0 = __float2bfloat16(v0), h1 = __float2bfloat16(v1);
        __nv_bfloat162 ph; ph.x = h0; ph.y = h1;
        __nv_bfloat162 pl;
        pl.x = __float2bfloat16(v0 - __bfloat162float(h0));
        pl.y = __float2bfloat16(v1 - __bfloat162float(h1));
        *reinterpret_cast<__nv_bfloat162*>(hb + (long long)nrow * GDIM + d2) = ph;
        *reinterpret_cast<__nv_bfloat162*>(lb + (long long)nrow * GDIM + d2) = pl;
    }
    // partial token norms over these 64 dims
    int tok = tid & 63, part = tid >> 6;
    float s = 0.f;
    #pragma unroll
    for (int i = 0; i < 16; i++) {
        float v = t[part * 16 + i][tok];
        s = fmaf(v, v, s);
    }
    nr[tid] = s;
    __syncthreads();
    if (tid < 64)
        g_xnp[((long long)(d0 >> 6) * BATCH + b) * GN + n0 + tid] =
            nr[tid] + nr[64 + tid] + nr[128 + tid] + nr[192 + tid];
}

// ---------------- reduce partial token norms -> invnorm --------------------
__global__ void invnorm_reduce_kernel() {
    int b = blockIdx.y;
    int t = blockIdx.x * 256 + threadIdx.x;
    float s = 0.f;
    #pragma unroll
    for (int d = 0; d < 8; d++)
        s += g_xnp[((long long)d * BATCH + b) * GN + t];
    g_invnorm[b * GN + t] = 1.f / fmaxf(sqrtf(s), 1e-12f);
}

// ---------------- HMMA bf16 GEMM (cp.async 3-stage, 2 CTA/SM) --------------
static constexpr int TAH = 0;
static constexpr int TAL = 8192;
static constexpr int TBH = 16384;
static constexpr int TBL = 24576;
static constexpr int STAGE = 32768;
static constexpr int NSTAGE = 3;
static constexpr int SMEM_TOTAL = NSTAGE * STAGE;  // 98304

template<bool SCALE_COL, bool BIAS, bool VSPLIT, bool HALF_OUT>
__global__ void __launch_bounds__(256, 2)
mma_gemm_kernel(const __nv_bfloat16* __restrict__ Ah_, const __nv_bfloat16* __restrict__ Al_,
                long long aBatch,
                const __nv_bfloat16* __restrict__ Bh_, const __nv_bfloat16* __restrict__ Bl_,
                long long bBatch,
                void* __restrict__ Cv, long long cBatch,
                int K, int nChunks,
                const float* __restrict__ colscale,
                const float* __restrict__ bias,
                __nv_bfloat16* __restrict__ vHi, __nv_bfloat16* __restrict__ vLo) {
    extern __shared__ char smem[];
    const uint32_t smem_u = smem_to_u32(smem);
    const int tid = threadIdx.x;
    const int lane = tid & 31, wid = tid >> 5;
    const int wm = wid & 3, wn = wid >> 2;     // 4 x 2 warps
    const int m0 = blockIdx.x * 128, n0 = blockIdx.y * 128, b = blockIdx.z;

    const char* Ah = (const char*)(Ah_ + (long long)b * aBatch);
    const char* Al = (const char*)(Al_ + (long long)b * aBatch);
    const char* Bh = (const char*)(Bh_ + (long long)b * bBatch);
    const char* Bl = (const char*)(Bl_ + (long long)b * bBatch);

    const int row0 = tid >> 2;
    const int chunk = tid & 3;
    const long long aoffA = ((long long)(m0 + row0) * K) * 2 + chunk * 16;
    const long long aoffB = ((long long)(m0 + row0 + 64) * K) * 2 + chunk * 16;
    const long long boffA = ((long long)(n0 + row0) * K) * 2 + chunk * 16;
    const long long boffB = ((long long)(n0 + row0 + 64) * K) * 2 + chunk * 16;
    const char* pa0 = Ah + aoffA;  const char* pa1 = Ah + aoffB;
    const char* pl0 = Al + aoffA;  const char* pl1 = Al + aoffB;
    const char* pb0 = Bh + boffA;  const char* pb1 = Bh + boffB;
    const char* pc0 = Bl + boffA;  const char* pc1 = Bl + boffB;
    const int s0 = swz(row0, chunk), s1 = swz(row0 + 64, chunk);

    float acc[2][8][4];
    #pragma unroll
    for (int i = 0; i < 2; i++)
        #pragma unroll
        for (int j = 0; j < 8; j++)
            #pragma unroll
            for (int q = 0; q < 4; q++) acc[i][j][q] = 0.f;

    auto issue = [&](int c) {
        uint32_t d = smem_u + (c % 3) * STAGE;
        long long ko = (long long)c * 64;
        CP_ASYNC16(d + TAH + s0, pa0 + ko);
        CP_ASYNC16(d + TAH + s1, pa1 + ko);
        CP_ASYNC16(d + TAL + s0, pl0 + ko);
        CP_ASYNC16(d + TAL + s1, pl1 + ko);
        CP_ASYNC16(d + TBH + s0, pb0 + ko);
        CP_ASYNC16(d + TBH + s1, pb1 + ko);
        CP_ASYNC16(d + TBL + s0, pc0 + ko);
        CP_ASYNC16(d + TBL + s1, pc1 + ko);
        CP_COMMIT();
    };
    issue(0); issue(1);

    const int a_r = wm * 32 + (lane & 15);
    const int a_ci = lane >> 4;
    const int b_r = wn * 64 + (lane & 7) + ((lane >> 4) << 3);
    const int b_ci = (lane >> 3) & 1;

    for (int c = 0; c < nChunks; c++) {
        CP_WAIT1();
        __syncthreads();
        if (c + 2 < nChunks) issue(c + 2); else CP_COMMIT();
        const uint32_t sb = smem_u + (c % 3) * STAGE;
        #pragma unroll
        for (int kk = 0; kk < 2; kk++) {
            uint32_t a_hi[2][4], a_lo[2][4], bf[4][4];
            #pragma unroll
            for (int mt = 0; mt < 2; mt++) {
                int r = a_r + mt * 16;
                uint32_t ar = sb + TAH + swz(r, kk * 2 + a_ci);
                ldsm4(a_hi[mt], ar);
                ldsm4(a_lo[mt], ar + (TAL - TAH));
            }
            #pragma unroll
            for (int p = 0; p < 4; p++) {
                int r = b_r + p * 16;
                ldsm4(bf[p], sb + TBH + swz(r, kk * 2 + b_ci));
            }
            #pragma unroll
            for (int mt = 0; mt < 2; mt++)
                #pragma unroll
                for (int p = 0; p < 4; p++) {
                    mma16816(acc[mt][2 * p],     a_hi[mt], &bf[p][0]);
                    mma16816(acc[mt][2 * p + 1], a_hi[mt], &bf[p][2]);
                    mma16816(acc[mt][2 * p],     a_lo[mt], &bf[p][0]);
                    mma16816(acc[mt][2 * p + 1], a_lo[mt], &bf[p][2]);
                }
            #pragma unroll
            for (int p = 0; p < 4; p++) {
                int r = b_r + p * 16;
                ldsm4(bf[p], sb + TBL + swz(r, kk * 2 + b_ci));
            }
            #pragma unroll
            for (int mt = 0; mt < 2; mt++)
                #pragma unroll
                for (int p = 0; p < 4; p++) {
                    mma16816(acc[mt][2 * p],     a_hi[mt], &bf[p][0]);
                    mma16816(acc[mt][2 * p + 1], a_hi[mt], &bf[p][2]);
                }
        }
    }
    CP_WAIT0();
    __syncthreads();

    float cs0[8], cs1[8];
    #pragma unroll
    for (int nt = 0; nt < 8; nt++) {
        if (SCALE_COL) {
            int col = wn * 64 + nt * 8 + (lane & 3) * 2;
            float2 cv = *(const float2*)(colscale + (long long)b * GN + n0 + col);
            cs0[nt] = cv.x; cs1[nt] = cv.y;
        } else { cs0[nt] = 1.f; cs1[nt] = 1.f; }
    }

    if (VSPLIT && blockIdx.x >= 4) {
        // v rows: transpose via smem, emit bf16 hi/lo K-major (token, chan)
        float* st = (float*)smem;   // 128 x 128, stride 129
        const int rl = wm * 32 + (lane >> 2);
        #pragma unroll
        for (int mt = 0; mt < 2; mt++) {
            #pragma unroll
            for (int nt = 0; nt < 8; nt++) {
                int col = wn * 64 + nt * 8 + (lane & 3) * 2;
                float* a = acc[mt][nt];
                int r0 = rl + mt * 16, r1 = r0 + 8;
                st[r0 * 129 + col] = a[0] * cs0[nt];
                st[r0 * 129 + col + 1] = a[1] * cs1[nt];
                st[r1 * 129 + col] = a[2] * cs0[nt];
                st[r1 * 129 + col + 1] = a[3] * cs1[nt];
            }
        }
        __syncthreads();
        int n = tid >> 1, half = tid & 1;
        int vc0 = (m0 - 512) + half * 64;
        __nv_bfloat16* hdst = vHi + ((long long)b * GN + n0 + n) * GDINNER + vc0;
        __nv_bfloat16* ldst = vLo + ((long long)b * GN + n0 + n) * GDINNER + vc0;
        #pragma unroll 8
        for (int j = 0; j < 64; j += 2) {
            float v0 = st[(half * 64 + j) * 129 + n];
            float v1 = st[(half * 64 + j + 1) * 129 + n];
            __nv_bfloat16 h0 = __float2bfloat16(v0), h1 = __float2bfloat16(v1);
            __nv_bfloat162 ph; ph.x = h0; ph.y = h1;
            __nv_bfloat162 pl;
            pl.x = __float2bfloat16(v0 - __bfloat162float(h0));
            pl.y = __float2bfloat16(v1 - __bfloat162float(h1));
            *reinterpret_cast<__nv_bfloat162*>(hdst + j) = ph;
            *reinterpret_cast<__nv_bfloat162*>(ldst + j) = pl;
        }
        return;
    }

    const int rbase = m0 + wm * 32 + (lane >> 2);
    #pragma unroll
    for (int mt = 0; mt < 2; mt++) {
        int r0 = rbase + mt * 16;
        int r1 = r0 + 8;
        float bv0 = 0.f, bv1 = 0.f;
        if (BIAS) { bv0 = bias[r0]; bv1 = bias[r1]; }
        if (HALF_OUT) {
            __half* c0row = (__half*)Cv + (long long)b * cBatch + (long long)r0 * GN + n0;
            __half* c1row = (__half*)Cv + (long long)b * cBatch + (long long)r1 * GN + n0;
            #pragma unroll
            for (int nt = 0; nt < 8; nt++) {
                int col = wn * 64 + nt * 8 + (lane & 3) * 2;
                float* a = acc[mt][nt];
                __half2 h0; h0.x = __float2half_rn(a[0] * cs0[nt]); h0.y = __float2half_rn(a[1] * cs1[nt]);
                __half2 h1; h1.x = __float2half_rn(a[2] * cs0[nt]); h1.y = __float2half_rn(a[3] * cs1[nt]);
                *(__half2*)(c0row + col) = h0;
                *(__half2*)(c1row + col) = h1;
            }
        } else {
            float* c0row = (float*)Cv + (long long)b * cBatch + (long long)r0 * GN + n0;
            float* c1row = (float*)Cv + (long long)b * cBatch + (long long)r1 * GN + n0;
            #pragma unroll
            for (int nt = 0; nt < 8; nt++) {
                int col = wn * 64 + nt * 8 + (lane & 3) * 2;
                float* a = acc[mt][nt];
                *(float2*)(c0row + col) = make_float2(a[0] * cs0[nt] + bv0, a[1] * cs1[nt] + bv0);
                *(float2*)(c1row + col) = make_float2(a[2] * cs0[nt] + bv1, a[3] * cs1[nt] + bv1);
            }
        }
    }
}

// ---------------- gram partials + channel norm partials --------------------
__global__ void __launch_bounds__(256) gram_kernel() {
    int p = blockIdx.x, h = blockIdx.y, b = blockIdx.z;
    __shared__ float qs[32 * 129];
    __shared__ float ks[32 * 129];
    int tid = threadIdx.x;
    int g = tid >> 6;
    int r = tid & 63;
    int i0 = (r >> 3) * 4;
    int j0 = (r & 7) * 4;
    float acc[4][4] = {};
    float nacc = 0.f;
    const int nch = tid & 63, nq = tid >> 6;   // norm: channel + col quarter
    const __half* qbase = g_QK + ((long long)b * 512 + h * 32) * GN + p * 1024;
    const __half* kbase = qbase + (long long)256 * GN;
    int lrow = tid >> 3;
    int lcol = (tid & 7) * 16;
    for (int t = 0; t < 8; t++) {
        long long nn0 = t * 128;
        __syncthreads();
        const __half* qr = qbase + (long long)lrow * GN + nn0 + lcol;
        const __half* kr = kbase + (long long)lrow * GN + nn0 + lcol;
        uint4 qu0 = *(const uint4*)(qr); uint4 qu1 = *(const uint4*)(qr + 8);
        uint4 ku0 = *(const uint4*)(kr); uint4 ku1 = *(const uint4*)(kr + 8);
        float* qd = qs + lrow * 129 + lcol;
        float* kd = ks + lrow * 129 + lcol;
        #pragma unroll
        for (int i = 0; i < 4; i++) {
            float2 f = __half22float2(((const __half2*)&qu0)[i]);
            qd[2 * i] = f.x; qd[2 * i + 1] = f.y;
            f = __half22float2(((const __half2*)&qu1)[i]);
            qd[8 + 2 * i] = f.x; qd[9 + 2 * i] = f.y;
            f = __half22float2(((const __half2*)&ku0)[i]);
            kd[2 * i] = f.x; kd[2 * i + 1] = f.y;
            f = __half22float2(((const __half2*)&ku1)[i]);
            kd[8 + 2 * i] = f.x; kd[9 + 2 * i] = f.y;
        }
        __syncthreads();
        #pragma unroll 8
        for (int s = 0; s < 32; s++) {
            int nn = g * 32 + s;
            float qv[4], kv[4];
            #pragma unroll
            for (int a = 0; a < 4; a++) qv[a] = qs[(i0 + a) * 129 + nn];
            #pragma unroll
            for (int a = 0; a < 4; a++) kv[a] = ks[(j0 + a) * 129 + nn];
            #pragma unroll
            for (int a = 0; a < 4; a++)
                #pragma unroll
                for (int cc = 0; cc < 4; cc++)
                    acc[a][cc] = fmaf(qv[a], kv[cc], acc[a][cc]);
        }
        // channel norm partials: channel nch (q<32, k>=32), cols nq*32..+31
        const float* src = (nch < 32) ? (qs + nch * 129) : (ks + (nch - 32) * 129);
        #pragma unroll 8
        for (int i = 0; i < 32; i++) {
            float v = src[nq * 32 + i];
            nacc = fmaf(v, v, nacc);
        }
    }
    __syncthreads();
    float* red = qs;
    #pragma unroll
    for (int a = 0; a < 4; a++)
        #pragma unroll
        for (int cc = 0; cc < 4; cc++)
            red[g * 1024 + (i0 + a) * 32 + (j0 + cc)] = acc[a][cc];
    ks[tid] = nacc;
    __syncthreads();
    for (int idx = tid; idx < 1024; idx += 256) {
        float sgm = red[idx] + red[1024 + idx] + red[2048 + idx] + red[3072 + idx];
        g_Gpart[(((long long)p * BATCH + b) * GHEADS + h) * 1024 + idx] = sgm;
    }
    if (tid < 64)
        g_Npart[(((long long)p * BATCH + b) * GHEADS + h) * 64 + tid] =
            ks[tid] + ks[64 + tid] + ks[128 + tid] + ks[192 + tid];
}

// ---------------- softmax + W2T = (attn-fold w_out), split -----------------
__global__ void attn_w2_kernel(const float* __restrict__ temp,
                               const float* __restrict__ w_out) {
    int h = blockIdx.x, b = blockIdx.y;
    __shared__ float Asm[1024];
    __shared__ float sinv[64];
    int tid = threadIdx.x;
    float tsc = 8.0f * expf(temp[h]);
    if (tid < 64) {
        float s = 0.f;
        #pragma unroll
        for (int p = 0; p < 8; p++)
            s += g_Npart[(((long long)p * BATCH + b) * GHEADS + h) * 64 + tid];
        sinv[tid] = 1.f / fmaxf(sqrtf(s), 1e-12f);
    }
    __syncthreads();
    for (int idx = tid; idx < 1024; idx += 256) {
        float s = 0.f;
        #pragma unroll
        for (int p = 0; p < 8; p++)
            s += g_Gpart[(((long long)p * BATCH + b) * GHEADS + h) * 1024 + idx];
        int i = idx >> 5, j = idx & 31;
        s *= tsc * sinv[i] * sinv[32 + j];
        Asm[idx] = s;
    }
    __syncthreads();
    int w = tid >> 5, lane = tid & 31;
    for (int t = 0; t < 4; t++) {
        int i = w + t * 8;
        float v = Asm[i * 32 + lane];
        float mx = v;
        for (int off = 16; off; off >>= 1) mx = fmaxf(mx, __shfl_xor_sync(~0u, mx, off));
        float e = expf(v - mx);
        float sm = e;
        for (int off = 16; off; off >>= 1) sm += __shfl_xor_sync(~0u, sm, off);
        Asm[i * 32 + lane] = e / sm;
    }
    __syncthreads();
    for (int idx = tid; idx < 32 * 512; idx += 256) {
        int j = idx & 31, c2 = idx >> 5;
        float s = 0.f;
        #pragma unroll
        for (int i = 0; i < 32; i++)
            s = fmaf(Asm[i * 32 + j], w_out[(h * 32 + i) * 512 + c2], s);
        long long o = ((long long)b * GDIM + c2) * GDINNER + h * 32 + j;
        __nv_bfloat16 hh = __float2bfloat16(s);
        g_W2T_hi[o] = hh;
        g_W2T_lo[o] = __float2bfloat16(s - __bfloat162float(hh));
    }
}

// ---------------- launch ----------------------------------------------------
extern "C" void kernel_launch(void* const* d_in, const int* in_sizes, int n_in,
                              void* d_out, int out_size) {
    const float* x      = (const float*)d_in[0];
    const float* gamma  = (const float*)d_in[2];
    const float* w_qkv  = (const float*)d_in[3];
    const float* temp   = (const float*)d_in[4];
    const float* w_out  = (const float*)d_in[5];
    const float* b_out  = (const float*)d_in[6];
    float* y = (float*)d_out;

    float* pInv;
    __half* pQK;
    __nv_bfloat16 *pWgh, *pWgl, *pXh, *pXl, *pVh, *pVl, *pW2h, *pW2l;
    cudaGetSymbolAddress((void**)&pInv, g_invnorm);
    cudaGetSymbolAddress((void**)&pQK,  g_QK);
    cudaGetSymbolAddress((void**)&pWgh, g_WgT_hi);
    cudaGetSymbolAddress((void**)&pWgl, g_WgT_lo);
    cudaGetSymbolAddress((void**)&pXh,  g_xT_hi);
    cudaGetSymbolAddress((void**)&pXl,  g_xT_lo);
    cudaGetSymbolAddress((void**)&pVh,  g_vT_hi);
    cudaGetSymbolAddress((void**)&pVl,  g_vT_lo);
    cudaGetSymbolAddress((void**)&pW2h, g_W2T_hi);
    cudaGetSymbolAddress((void**)&pW2l, g_W2T_lo);

    cudaFuncSetAttribute(mma_gemm_kernel<true, false, true, true>,
                         cudaFuncAttributeMaxDynamicSharedMemorySize, SMEM_TOTAL);
    cudaFuncSetAttribute(mma_gemm_kernel<false, true, false, false>,
                         cudaFuncAttributeMaxDynamicSharedMemorySize, SMEM_TOTAL);

    prep_wg_kernel<<<(GDIM * GM1) / 256, 256>>>(w_qkv, gamma);
    transpose_split_kernel<<<dim3(GN / 64, GDIM / 64, BATCH), 256>>>(x, pXh, pXl);
    invnorm_reduce_kernel<<<dim3(GN / 256, BATCH), 256>>>();

    // QKV: q,k rows -> fp16 g_QK; v rows -> vT bf16 hi/lo directly
    mma_gemm_kernel<true, false, true, true><<<dim3(GM1 / 128, GN / 128, BATCH), 256, SMEM_TOTAL>>>(
        pWgh, pWgl, 0LL,
        pXh, pXl, (long long)GN * GDIM,
        pQK, (long long)512 * GN,
        GDIM, GDIM / 32, pInv, nullptr, pVh, pVl);

    gram_kernel<<<dim3(8, GHEADS, BATCH), 256>>>();
    attn_w2_kernel<<<dim3(GHEADS, BATCH), 256>>>(temp, w_out);

    // y[b] (512 x 8192) = W2T[b] (512x256) @ vT[b]^T + b_out
    mma_gemm_kernel<false, true, false, false><<<dim3(GDIM / 128, GN / 128, BATCH), 256, SMEM_TOTAL>>>(
        pW2h, pW2l, (long long)GDIM * GDINNER,
        pVh, pVl, (long long)GN * GDINNER,
        y, (long long)GDIM * GN,
        GDINNER, GDINNER / 32, nullptr, b_out, nullptr, nullptr);
}

// round 12
// speedup vs baseline: 1.5787x; 1.5787x over previous
#include <cuda_runtime.h>
#include <cuda_fp16.h>
#include <math.h>
#include <cstdint>

#define BATCH 8
#define GN 8192
#define GDIM 512
#define GHEADS 8
#define GM1 768
#define GDINNER 256

// ---------------- scratch ---------------------------------------------------
__device__ __align__(128) __half g_WgT_hi[GM1 * GDIM];
__device__ __align__(128) __half g_WgT_lo[GM1 * GDIM];
__device__ __align__(128) __half g_xT_hi[(long long)BATCH * GN * GDIM];
__device__ __align__(128) __half g_xT_lo[(long long)BATCH * GN * GDIM];
__device__ __align__(128) __half g_vT_hi[(long long)BATCH * GN * GDINNER];
__device__ __align__(128) __half g_vT_lo[(long long)BATCH * GN * GDINNER];
__device__ __align__(128) __half g_W2T_hi[BATCH * GDIM * GDINNER];
__device__ __align__(128) __half g_W2T_lo[BATCH * GDIM * GDINNER];
__device__ __align__(128) __half g_QK[(long long)BATCH * 512 * GN];   // q,k fp16
__device__ float g_xnp[8 * BATCH * GN];
__device__ float g_invnorm[BATCH * GN];
__device__ float g_Gpart[8 * BATCH * GHEADS * 32 * 32];
__device__ float g_Npart[8 * BATCH * GHEADS * 64];

// ---------------- helpers ---------------------------------------------------
__device__ __forceinline__ uint32_t smem_to_u32(const void* p) {
    uint32_t a;
    asm("{ .reg .u64 t; cvta.to.shared.u64 t, %1; cvt.u32.u64 %0, t; }" : "=r"(a) : "l"(p));
    return a;
}
__device__ __forceinline__ void ldsm4(uint32_t* r, uint32_t addr) {
    asm volatile("ldmatrix.sync.aligned.m8n8.x4.shared.b16 {%0,%1,%2,%3}, [%4];"
                 : "=r"(r[0]), "=r"(r[1]), "=r"(r[2]), "=r"(r[3]) : "r"(addr));
}
__device__ __forceinline__ void mma16816(float* d, const uint32_t* a, const uint32_t* b) {
    asm volatile("mma.sync.aligned.m16n8k16.row.col.f32.f16.f16.f32 "
                 "{%0,%1,%2,%3}, {%4,%5,%6,%7}, {%8,%9}, {%0,%1,%2,%3};"
                 : "+f"(d[0]), "+f"(d[1]), "+f"(d[2]), "+f"(d[3])
                 : "r"(a[0]), "r"(a[1]), "r"(a[2]), "r"(a[3]), "r"(b[0]), "r"(b[1]));
}
#define CP_ASYNC16(dst, src) \
    asm volatile("cp.async.cg.shared.global [%0], [%1], 16;" :: "r"(dst), "l"(src))
#define CP_COMMIT() asm volatile("cp.async.commit_group;")
#define CP_WAIT1()  asm volatile("cp.async.wait_group 1;")
#define CP_WAIT0()  asm volatile("cp.async.wait_group 0;")

__device__ __forceinline__ int swz(int row, int ci) {
    return row * 64 + ((ci ^ ((row >> 1) & 3)) << 4);
}
__device__ __forceinline__ __half2 split_hi(float v0, float v1, __half2& lo) {
    __half h0 = __float2half_rn(v0), h1 = __float2half_rn(v1);
    lo = __halves2half2(__float2half_rn(v0 - __half2float(h0)),
                        __float2half_rn(v1 - __half2float(h1)));
    return __halves2half2(h0, h1);
}

// ---------------- kernel 0: fold gamma*sqrt(dim) into W, split -------------
__global__ void prep_wg_kernel(const float* __restrict__ w_qkv,
                               const float* __restrict__ gamma) {
    int idx = blockIdx.x * 256 + threadIdx.x;   // over 768*512; out [m][d]
    int m = idx >> 9, d = idx & 511;
    float v = w_qkv[d * GM1 + m] * gamma[d] * 22.627416997969522f;
    __half h = __float2half_rn(v);
    g_WgT_hi[idx] = h;
    g_WgT_lo[idx] = __float2half_rn(v - __half2float(h));
}

// ---------------- transpose + split x (fp16), + partial token norms --------
__global__ void transpose_split_kernel(const float* __restrict__ src) {
    __shared__ float t[64][65];
    __shared__ float nr[256];
    int n0 = blockIdx.x * 64, d0 = blockIdx.y * 64, b = blockIdx.z;
    int tid = threadIdx.x;
    int c = tid & 63, r4 = tid >> 6;
    const float* sb = src + ((long long)b * GDIM + d0) * GN + n0;
    #pragma unroll
    for (int i = 0; i < 16; i++) {
        int row = r4 + i * 4;
        t[row][c] = sb[(long long)row * GN + c];
    }
    __syncthreads();
    int d2 = (tid & 31) * 2, rw = tid >> 5;
    __half* hb = g_xT_hi + ((long long)b * GN + n0) * GDIM + d0;
    __half* lb = g_xT_lo + ((long long)b * GN + n0) * GDIM + d0;
    #pragma unroll
    for (int i = 0; i < 8; i++) {
        int nrow = rw + i * 8;
        __half2 pl;
        __half2 ph = split_hi(t[d2][nrow], t[d2 + 1][nrow], pl);
        *reinterpret_cast<__half2*>(hb + (long long)nrow * GDIM + d2) = ph;
        *reinterpret_cast<__half2*>(lb + (long long)nrow * GDIM + d2) = pl;
    }
    // partial token norms over these 64 dims
    int tok = tid & 63, part = tid >> 6;
    float s = 0.f;
    #pragma unroll
    for (int i = 0; i < 16; i++) {
        float v = t[part * 16 + i][tok];
        s = fmaf(v, v, s);
    }
    nr[tid] = s;
    __syncthreads();
    if (tid < 64)
        g_xnp[((long long)(d0 >> 6) * BATCH + b) * GN + n0 + tid] =
            nr[tid] + nr[64 + tid] + nr[128 + tid] + nr[192 + tid];
}

// ---------------- reduce partial token norms -> invnorm --------------------
__global__ void invnorm_reduce_kernel() {
    int b = blockIdx.y;
    int t = blockIdx.x * 256 + threadIdx.x;
    float s = 0.f;
    #pragma unroll
    for (int d = 0; d < 8; d++)
        s += g_xnp[((long long)d * BATCH + b) * GN + t];
    g_invnorm[b * GN + t] = 1.f / fmaxf(sqrtf(s), 1e-12f);
}

// ---------------- HMMA fp16 GEMM (cp.async 3-stage, 2 CTA/SM) --------------
// C[b](MxGN) = A(MxK) @ B[b](GNxK)^T, tile 128Mx128Nx32K, 256 thr (4x2 warps).
// fp16 hi/lo: D = Ah*Bh + Al*Bh (+ Ah*Bl unless skipBl).
static constexpr int TAH = 0;
static constexpr int TAL = 8192;
static constexpr int TBH = 16384;
static constexpr int TBL = 24576;
static constexpr int STAGE = 32768;
static constexpr int NSTAGE = 3;
static constexpr int SMEM_TOTAL = NSTAGE * STAGE;  // 98304

template<bool SCALE_COL, bool BIAS, bool VSPLIT, bool HALF_OUT>
__global__ void __launch_bounds__(256, 2)
mma_gemm_kernel(const __half* __restrict__ Ah_, const __half* __restrict__ Al_,
                long long aBatch,
                const __half* __restrict__ Bh_, const __half* __restrict__ Bl_,
                long long bBatch,
                void* __restrict__ Cv, long long cBatch,
                int K, int nChunks,
                const float* __restrict__ colscale,
                const float* __restrict__ bias,
                __half* __restrict__ vHi, __half* __restrict__ vLo) {
    extern __shared__ char smem[];
    const uint32_t smem_u = smem_to_u32(smem);
    const int tid = threadIdx.x;
    const int lane = tid & 31, wid = tid >> 5;
    const int wm = wid & 3, wn = wid >> 2;
    const int m0 = blockIdx.x * 128, n0 = blockIdx.y * 128, b = blockIdx.z;
    // q,k rows: drop Ah*Bl correction (error ~2.8e-4 pre-norm, ~7e-5 final)
    const bool skipBl = VSPLIT && (blockIdx.x < 4);

    const char* Ah = (const char*)(Ah_ + (long long)b * aBatch);
    const char* Al = (const char*)(Al_ + (long long)b * aBatch);
    const char* Bh = (const char*)(Bh_ + (long long)b * bBatch);
    const char* Bl = (const char*)(Bl_ + (long long)b * bBatch);

    const int row0 = tid >> 2;
    const int chunk = tid & 3;
    const long long aoffA = ((long long)(m0 + row0) * K) * 2 + chunk * 16;
    const long long aoffB = ((long long)(m0 + row0 + 64) * K) * 2 + chunk * 16;
    const long long boffA = ((long long)(n0 + row0) * K) * 2 + chunk * 16;
    const long long boffB = ((long long)(n0 + row0 + 64) * K) * 2 + chunk * 16;
    const char* pa0 = Ah + aoffA;  const char* pa1 = Ah + aoffB;
    const char* pl0 = Al + aoffA;  const char* pl1 = Al + aoffB;
    const char* pb0 = Bh + boffA;  const char* pb1 = Bh + boffB;
    const char* pc0 = Bl + boffA;  const char* pc1 = Bl + boffB;
    const int s0 = swz(row0, chunk), s1 = swz(row0 + 64, chunk);

    float acc[2][8][4];
    #pragma unroll
    for (int i = 0; i < 2; i++)
        #pragma unroll
        for (int j = 0; j < 8; j++)
            #pragma unroll
            for (int q = 0; q < 4; q++) acc[i][j][q] = 0.f;

    auto issue = [&](int c) {
        uint32_t d = smem_u + (c % 3) * STAGE;
        long long ko = (long long)c * 64;
        CP_ASYNC16(d + TAH + s0, pa0 + ko);
        CP_ASYNC16(d + TAH + s1, pa1 + ko);
        CP_ASYNC16(d + TAL + s0, pl0 + ko);
        CP_ASYNC16(d + TAL + s1, pl1 + ko);
        CP_ASYNC16(d + TBH + s0, pb0 + ko);
        CP_ASYNC16(d + TBH + s1, pb1 + ko);
        if (!skipBl) {
            CP_ASYNC16(d + TBL + s0, pc0 + ko);
            CP_ASYNC16(d + TBL + s1, pc1 + ko);
        }
        CP_COMMIT();
    };
    issue(0); issue(1);

    const int a_r = wm * 32 + (lane & 15);
    const int a_ci = lane >> 4;
    const int b_r = wn * 64 + (lane & 7) + ((lane >> 4) << 3);
    const int b_ci = (lane >> 3) & 1;

    for (int c = 0; c < nChunks; c++) {
        CP_WAIT1();
        __syncthreads();
        if (c + 2 < nChunks) issue(c + 2); else CP_COMMIT();
        const uint32_t sb = smem_u + (c % 3) * STAGE;
        #pragma unroll
        for (int kk = 0; kk < 2; kk++) {
            uint32_t a_hi[2][4], a_lo[2][4], bf[4][4];
            #pragma unroll
            for (int mt = 0; mt < 2; mt++) {
                int r = a_r + mt * 16;
                uint32_t ar = sb + TAH + swz(r, kk * 2 + a_ci);
                ldsm4(a_hi[mt], ar);
                ldsm4(a_lo[mt], ar + (TAL - TAH));
            }
            #pragma unroll
            for (int p = 0; p < 4; p++) {
                int r = b_r + p * 16;
                ldsm4(bf[p], sb + TBH + swz(r, kk * 2 + b_ci));
            }
            #pragma unroll
            for (int mt = 0; mt < 2; mt++)
                #pragma unroll
                for (int p = 0; p < 4; p++) {
                    mma16816(acc[mt][2 * p],     a_hi[mt], &bf[p][0]);
                    mma16816(acc[mt][2 * p + 1], a_hi[mt], &bf[p][2]);
                    mma16816(acc[mt][2 * p],     a_lo[mt], &bf[p][0]);
                    mma16816(acc[mt][2 * p + 1], a_lo[mt], &bf[p][2]);
                }
            if (!skipBl) {
                #pragma unroll
                for (int p = 0; p < 4; p++) {
                    int r = b_r + p * 16;
                    ldsm4(bf[p], sb + TBL + swz(r, kk * 2 + b_ci));
                }
                #pragma unroll
                for (int mt = 0; mt < 2; mt++)
                    #pragma unroll
                    for (int p = 0; p < 4; p++) {
                        mma16816(acc[mt][2 * p],     a_hi[mt], &bf[p][0]);
                        mma16816(acc[mt][2 * p + 1], a_hi[mt], &bf[p][2]);
                    }
            }
        }
    }
    CP_WAIT0();
    __syncthreads();

    float cs0[8], cs1[8];
    #pragma unroll
    for (int nt = 0; nt < 8; nt++) {
        if (SCALE_COL) {
            int col = wn * 64 + nt * 8 + (lane & 3) * 2;
            float2 cv = *(const float2*)(colscale + (long long)b * GN + n0 + col);
            cs0[nt] = cv.x; cs1[nt] = cv.y;
        } else { cs0[nt] = 1.f; cs1[nt] = 1.f; }
    }

    if (VSPLIT && blockIdx.x >= 4) {
        // v rows: transpose via smem, emit fp16 hi/lo K-major (token, chan)
        float* st = (float*)smem;   // 128 x 128, stride 129
        const int rl = wm * 32 + (lane >> 2);
        #pragma unroll
        for (int mt = 0; mt < 2; mt++) {
            #pragma unroll
            for (int nt = 0; nt < 8; nt++) {
                int col = wn * 64 + nt * 8 + (lane & 3) * 2;
                float* a = acc[mt][nt];
                int r0 = rl + mt * 16, r1 = r0 + 8;
                st[r0 * 129 + col] = a[0] * cs0[nt];
                st[r0 * 129 + col + 1] = a[1] * cs1[nt];
                st[r1 * 129 + col] = a[2] * cs0[nt];
                st[r1 * 129 + col + 1] = a[3] * cs1[nt];
            }
        }
        __syncthreads();
        int n = tid >> 1, half = tid & 1;
        int vc0 = (m0 - 512) + half * 64;
        __half* hdst = vHi + ((long long)b * GN + n0 + n) * GDINNER + vc0;
        __half* ldst = vLo + ((long long)b * GN + n0 + n) * GDINNER + vc0;
        #pragma unroll 8
        for (int j = 0; j < 64; j += 2) {
            __half2 pl;
            __half2 ph = split_hi(st[(half * 64 + j) * 129 + n],
                                  st[(half * 64 + j + 1) * 129 + n], pl);
            *reinterpret_cast<__half2*>(hdst + j) = ph;
            *reinterpret_cast<__half2*>(ldst + j) = pl;
        }
        return;
    }

    const int rbase = m0 + wm * 32 + (lane >> 2);
    #pragma unroll
    for (int mt = 0; mt < 2; mt++) {
        int r0 = rbase + mt * 16;
        int r1 = r0 + 8;
        float bv0 = 0.f, bv1 = 0.f;
        if (BIAS) { bv0 = bias[r0]; bv1 = bias[r1]; }
        if (HALF_OUT) {
            __half* c0row = (__half*)Cv + (long long)b * cBatch + (long long)r0 * GN + n0;
            __half* c1row = (__half*)Cv + (long long)b * cBatch + (long long)r1 * GN + n0;
            #pragma unroll
            for (int nt = 0; nt < 8; nt++) {
                int col = wn * 64 + nt * 8 + (lane & 3) * 2;
                float* a = acc[mt][nt];
                *(__half2*)(c0row + col) =
                    __halves2half2(__float2half_rn(a[0] * cs0[nt]), __float2half_rn(a[1] * cs1[nt]));
                *(__half2*)(c1row + col) =
                    __halves2half2(__float2half_rn(a[2] * cs0[nt]), __float2half_rn(a[3] * cs1[nt]));
            }
        } else {
            float* c0row = (float*)Cv + (long long)b * cBatch + (long long)r0 * GN + n0;
            float* c1row = (float*)Cv + (long long)b * cBatch + (long long)r1 * GN + n0;
            #pragma unroll
            for (int nt = 0; nt < 8; nt++) {
                int col = wn * 64 + nt * 8 + (lane & 3) * 2;
                float* a = acc[mt][nt];
                *(float2*)(c0row + col) = make_float2(a[0] * cs0[nt] + bv0, a[1] * cs1[nt] + bv0);
                *(float2*)(c1row + col) = make_float2(a[2] * cs0[nt] + bv1, a[3] * cs1[nt] + bv1);
            }
        }
    }
}

// ---------------- gram partials + channel norm partials (fp16 reads) -------
__global__ void __launch_bounds__(256) gram_kernel() {
    int p = blockIdx.x, h = blockIdx.y, b = blockIdx.z;
    __shared__ float qs[32 * 129];
    __shared__ float ks[32 * 129];
    int tid = threadIdx.x;
    int g = tid >> 6;
    int r = tid & 63;
    int i0 = (r >> 3) * 4;
    int j0 = (r & 7) * 4;
    float acc[4][4] = {};
    float nacc = 0.f;
    const int nch = tid & 63, nq = tid >> 6;
    const __half* qbase = g_QK + ((long long)b * 512 + h * 32) * GN + p * 1024;
    const __half* kbase = qbase + (long long)256 * GN;
    int lrow = tid >> 3;
    int lcol = (tid & 7) * 16;
    for (int t = 0; t < 8; t++) {
        long long nn0 = t * 128;
        __syncthreads();
        const __half* qr = qbase + (long long)lrow * GN + nn0 + lcol;
        const __half* kr = kbase + (long long)lrow * GN + nn0 + lcol;
        uint4 qu0 = *(const uint4*)(qr); uint4 qu1 = *(const uint4*)(qr + 8);
        uint4 ku0 = *(const uint4*)(kr); uint4 ku1 = *(const uint4*)(kr + 8);
        float* qd = qs + lrow * 129 + lcol;
        float* kd = ks + lrow * 129 + lcol;
        #pragma unroll
        for (int i = 0; i < 4; i++) {
            float2 f = __half22float2(((const __half2*)&qu0)[i]);
            qd[2 * i] = f.x; qd[2 * i + 1] = f.y;
            f = __half22float2(((const __half2*)&qu1)[i]);
            qd[8 + 2 * i] = f.x; qd[9 + 2 * i] = f.y;
            f = __half22float2(((const __half2*)&ku0)[i]);
            kd[2 * i] = f.x; kd[2 * i + 1] = f.y;
            f = __half22float2(((const __half2*)&ku1)[i]);
            kd[8 + 2 * i] = f.x; kd[9 + 2 * i] = f.y;
        }
        __syncthreads();
        #pragma unroll 8
        for (int s = 0; s < 32; s++) {
            int nn = g * 32 + s;
            float qv[4], kv[4];
            #pragma unroll
            for (int a = 0; a < 4; a++) qv[a] = qs[(i0 + a) * 129 + nn];
            #pragma unroll
            for (int a = 0; a < 4; a++) kv[a] = ks[(j0 + a) * 129 + nn];
            #pragma unroll
            for (int a = 0; a < 4; a++)
                #pragma unroll
                for (int cc = 0; cc < 4; cc++)
                    acc[a][cc] = fmaf(qv[a], kv[cc], acc[a][cc]);
        }
        const float* src = (nch < 32) ? (qs + nch * 129) : (ks + (nch - 32) * 129);
        #pragma unroll 8
        for (int i = 0; i < 32; i++) {
            float v = src[nq * 32 + i];
            nacc = fmaf(v, v, nacc);
        }
    }
    __syncthreads();
    float* red = qs;
    #pragma unroll
    for (int a = 0; a < 4; a++)
        #pragma unroll
        for (int cc = 0; cc < 4; cc++)
            red[g * 1024 + (i0 + a) * 32 + (j0 + cc)] = acc[a][cc];
    ks[tid] = nacc;
    __syncthreads();
    for (int idx = tid; idx < 1024; idx += 256) {
        float sgm = red[idx] + red[1024 + idx] + red[2048 + idx] + red[3072 + idx];
        g_Gpart[(((long long)p * BATCH + b) * GHEADS + h) * 1024 + idx] = sgm;
    }
    if (tid < 64)
        g_Npart[(((long long)p * BATCH + b) * GHEADS + h) * 64 + tid] =
            ks[tid] + ks[64 + tid] + ks[128 + tid] + ks[192 + tid];
}

// ---------------- softmax + W2T = (attn-fold w_out), fp16 split ------------
__global__ void attn_w2_kernel(const float* __restrict__ temp,
                               const float* __restrict__ w_out) {
    int h = blockIdx.x, b = blockIdx.y;
    __shared__ float Asm[1024];
    __shared__ float sinv[64];
    int tid = threadIdx.x;
    float tsc = 8.0f * expf(temp[h]);
    if (tid < 64) {
        float s = 0.f;
        #pragma unroll
        for (int p = 0; p < 8; p++)
            s += g_Npart[(((long long)p * BATCH + b) * GHEADS + h) * 64 + tid];
        sinv[tid] = 1.f / fmaxf(sqrtf(s), 1e-12f);
    }
    __syncthreads();
    for (int idx = tid; idx < 1024; idx += 256) {
        float s = 0.f;
        #pragma unroll
        for (int p = 0; p < 8; p++)
            s += g_Gpart[(((long long)p * BATCH + b) * GHEADS + h) * 1024 + idx];
        int i = idx >> 5, j = idx & 31;
        s *= tsc * sinv[i] * sinv[32 + j];
        Asm[idx] = s;
    }
    __syncthreads();
    int w = tid >> 5, lane = tid & 31;
    for (int t = 0; t < 4; t++) {
        int i = w + t * 8;
        float v = Asm[i * 32 + lane];
        float mx = v;
        for (int off = 16; off; off >>= 1) mx = fmaxf(mx, __shfl_xor_sync(~0u, mx, off));
        float e = expf(v - mx);
        float sm = e;
        for (int off = 16; off; off >>= 1) sm += __shfl_xor_sync(~0u, sm, off);
        Asm[i * 32 + lane] = e / sm;
    }
    __syncthreads();
    for (int idx = tid; idx < 32 * 512; idx += 256) {
        int j = idx & 31, c2 = idx >> 5;
        float s = 0.f;
        #pragma unroll
        for (int i = 0; i < 32; i++)
            s = fmaf(Asm[i * 32 + j], w_out[(h * 32 + i) * 512 + c2], s);
        long long o = ((long long)b * GDIM + c2) * GDINNER + h * 32 + j;
        __half hh = __float2half_rn(s);
        g_W2T_hi[o] = hh;
        g_W2T_lo[o] = __float2half_rn(s - __half2float(hh));
    }
}

// ---------------- launch ----------------------------------------------------
extern "C" void kernel_launch(void* const* d_in, const int* in_sizes, int n_in,
                              void* d_out, int out_size) {
    const float* x      = (const float*)d_in[0];
    const float* gamma  = (const float*)d_in[2];
    const float* w_qkv  = (const float*)d_in[3];
    const float* temp   = (const float*)d_in[4];
    const float* w_out  = (const float*)d_in[5];
    const float* b_out  = (const float*)d_in[6];
    float* y = (float*)d_out;

    float* pInv;
    __half *pQK, *pWgh, *pWgl, *pXh, *pXl, *pVh, *pVl, *pW2h, *pW2l;
    cudaGetSymbolAddress((void**)&pInv, g_invnorm);
    cudaGetSymbolAddress((void**)&pQK,  g_QK);
    cudaGetSymbolAddress((void**)&pWgh, g_WgT_hi);
    cudaGetSymbolAddress((void**)&pWgl, g_WgT_lo);
    cudaGetSymbolAddress((void**)&pXh,  g_xT_hi);
    cudaGetSymbolAddress((void**)&pXl,  g_xT_lo);
    cudaGetSymbolAddress((void**)&pVh,  g_vT_hi);
    cudaGetSymbolAddress((void**)&pVl,  g_vT_lo);
    cudaGetSymbolAddress((void**)&pW2h, g_W2T_hi);
    cudaGetSymbolAddress((void**)&pW2l, g_W2T_lo);

    cudaFuncSetAttribute(mma_gemm_kernel<true, false, true, true>,
                         cudaFuncAttributeMaxDynamicSharedMemorySize, SMEM_TOTAL);
    cudaFuncSetAttribute(mma_gemm_kernel<false, true, false, false>,
                         cudaFuncAttributeMaxDynamicSharedMemorySize, SMEM_TOTAL);

    prep_wg_kernel<<<(GDIM * GM1) / 256, 256>>>(w_qkv, gamma);
    transpose_split_kernel<<<dim3(GN / 64, GDIM / 64, BATCH), 256>>>(x);
    invnorm_reduce_kernel<<<dim3(GN / 256, BATCH), 256>>>();

    // QKV: q,k rows (2-pass) -> fp16 g_QK; v rows (3-pass) -> vT fp16 hi/lo
    mma_gemm_kernel<true, false, true, true><<<dim3(GM1 / 128, GN / 128, BATCH), 256, SMEM_TOTAL>>>(
        pWgh, pWgl, 0LL,
        pXh, pXl, (long long)GN * GDIM,
        pQK, (long long)512 * GN,
        GDIM, GDIM / 32, pInv, nullptr, pVh, pVl);

    gram_kernel<<<dim3(8, GHEADS, BATCH), 256>>>();
    attn_w2_kernel<<<dim3(GHEADS, BATCH), 256>>>(temp, w_out);

    // y[b] (512 x 8192) = W2T[b] (512x256) @ vT[b]^T + b_out  (3-pass)
    mma_gemm_kernel<false, true, false, false><<<dim3(GDIM / 128, GN / 128, BATCH), 256, SMEM_TOTAL>>>(
        pW2h, pW2l, (long long)GDIM * GDINNER,
        pVh, pVl, (long long)GN * GDINNER,
        y, (long long)GDIM * GN,
        GDINNER, GDINNER / 32, nullptr, b_out, nullptr, nullptr);
}

// round 13
// speedup vs baseline: 1.7091x; 1.0826x over previous
#include <cuda_runtime.h>
#include <cuda_fp16.h>
#include <math.h>
#include <cstdint>

#define BATCH 8
#define GN 8192
#define GDIM 512
#define GHEADS 8
#define GM1 768
#define GDINNER 256

// ---------------- scratch ---------------------------------------------------
__device__ __align__(128) __half g_WgT_hi[GM1 * GDIM];
__device__ __align__(128) __half g_WgT_lo[GM1 * GDIM];
__device__ __align__(128) __half g_xT_hi[(long long)BATCH * GN * GDIM];
__device__ __align__(128) __half g_xT_lo[(long long)BATCH * GN * GDIM];
__device__ __align__(128) __half g_vT_hi[(long long)BATCH * GN * GDINNER];
__device__ __align__(128) __half g_vT_lo[(long long)BATCH * GN * GDINNER];
__device__ __align__(128) __half g_W2T_hi[BATCH * GDIM * GDINNER];
__device__ __align__(128) __half g_W2T_lo[BATCH * GDIM * GDINNER];
__device__ __align__(128) __half g_QK[(long long)BATCH * 512 * GN];   // q,k fp16
__device__ float g_xnp[8 * BATCH * GN];
__device__ float g_invnorm[BATCH * GN];
__device__ float g_Gpart[8 * BATCH * GHEADS * 32 * 32];
__device__ float g_Npart[8 * BATCH * GHEADS * 64];

// ---------------- helpers ---------------------------------------------------
__device__ __forceinline__ uint32_t smem_to_u32(const void* p) {
    uint32_t a;
    asm("{ .reg .u64 t; cvta.to.shared.u64 t, %1; cvt.u32.u64 %0, t; }" : "=r"(a) : "l"(p));
    return a;
}
__device__ __forceinline__ void ldsm4(uint32_t* r, uint32_t addr) {
    asm volatile("ldmatrix.sync.aligned.m8n8.x4.shared.b16 {%0,%1,%2,%3}, [%4];"
                 : "=r"(r[0]), "=r"(r[1]), "=r"(r[2]), "=r"(r[3]) : "r"(addr));
}
__device__ __forceinline__ void mma16816(float* d, const uint32_t* a, const uint32_t* b) {
    asm volatile("mma.sync.aligned.m16n8k16.row.col.f32.f16.f16.f32 "
                 "{%0,%1,%2,%3}, {%4,%5,%6,%7}, {%8,%9}, {%0,%1,%2,%3};"
                 : "+f"(d[0]), "+f"(d[1]), "+f"(d[2]), "+f"(d[3])
                 : "r"(a[0]), "r"(a[1]), "r"(a[2]), "r"(a[3]), "r"(b[0]), "r"(b[1]));
}
#define CP_ASYNC16(dst, src) \
    asm volatile("cp.async.cg.shared.global [%0], [%1], 16;" :: "r"(dst), "l"(src))
#define CP_COMMIT() asm volatile("cp.async.commit_group;")
#define CP_WAIT1()  asm volatile("cp.async.wait_group 1;")
#define CP_WAIT0()  asm volatile("cp.async.wait_group 0;")

__device__ __forceinline__ int swz(int row, int ci) {
    return row * 64 + ((ci ^ ((row >> 1) & 3)) << 4);
}
__device__ __forceinline__ __half2 split_hi(float v0, float v1, __half2& lo) {
    __half h0 = __float2half_rn(v0), h1 = __float2half_rn(v1);
    lo = __halves2half2(__float2half_rn(v0 - __half2float(h0)),
                        __float2half_rn(v1 - __half2float(h1)));
    return __halves2half2(h0, h1);
}

// ---------------- kernel 0: fold gamma*sqrt(dim) into W, split -------------
__global__ void prep_wg_kernel(const float* __restrict__ w_qkv,
                               const float* __restrict__ gamma) {
    int idx = blockIdx.x * 256 + threadIdx.x;   // over 768*512; out [m][d]
    int m = idx >> 9, d = idx & 511;
    float v = w_qkv[d * GM1 + m] * gamma[d] * 22.627416997969522f;
    __half h = __float2half_rn(v);
    g_WgT_hi[idx] = h;
    g_WgT_lo[idx] = __float2half_rn(v - __half2float(h));
}

// ---------------- transpose + split x (fp16), + partial token norms --------
__global__ void transpose_split_kernel(const float* __restrict__ src) {
    __shared__ float t[64][65];
    __shared__ float nr[256];
    int n0 = blockIdx.x * 64, d0 = blockIdx.y * 64, b = blockIdx.z;
    int tid = threadIdx.x;
    int c = tid & 63, r4 = tid >> 6;
    const float* sb = src + ((long long)b * GDIM + d0) * GN + n0;
    #pragma unroll
    for (int i = 0; i < 16; i++) {
        int row = r4 + i * 4;
        t[row][c] = sb[(long long)row * GN + c];
    }
    __syncthreads();
    int d2 = (tid & 31) * 2, rw = tid >> 5;
    __half* hb = g_xT_hi + ((long long)b * GN + n0) * GDIM + d0;
    __half* lb = g_xT_lo + ((long long)b * GN + n0) * GDIM + d0;
    #pragma unroll
    for (int i = 0; i < 8; i++) {
        int nrow = rw + i * 8;
        __half2 pl;
        __half2 ph = split_hi(t[d2][nrow], t[d2 + 1][nrow], pl);
        *reinterpret_cast<__half2*>(hb + (long long)nrow * GDIM + d2) = ph;
        *reinterpret_cast<__half2*>(lb + (long long)nrow * GDIM + d2) = pl;
    }
    // partial token norms over these 64 dims
    int tok = tid & 63, part = tid >> 6;
    float s = 0.f;
    #pragma unroll
    for (int i = 0; i < 16; i++) {
        float v = t[part * 16 + i][tok];
        s = fmaf(v, v, s);
    }
    nr[tid] = s;
    __syncthreads();
    if (tid < 64)
        g_xnp[((long long)(d0 >> 6) * BATCH + b) * GN + n0 + tid] =
            nr[tid] + nr[64 + tid] + nr[128 + tid] + nr[192 + tid];
}

// ---------------- reduce partial token norms -> invnorm --------------------
__global__ void invnorm_reduce_kernel() {
    int b = blockIdx.y;
    int t = blockIdx.x * 256 + threadIdx.x;
    float s = 0.f;
    #pragma unroll
    for (int d = 0; d < 8; d++)
        s += g_xnp[((long long)d * BATCH + b) * GN + t];
    g_invnorm[b * GN + t] = 1.f / fmaxf(sqrtf(s), 1e-12f);
}

// ---------------- HMMA fp16 GEMM (cp.async 3-stage, 2 CTA/SM) --------------
// C[b](MxGN) = A(MxK) @ B[b](GNxK)^T, tile 128Mx128Nx32K, 256 thr (4x2 warps).
// fp16 hi/lo: 3-pass D = Ah*Bh + Al*Bh + Ah*Bl; q,k blocks use 1-pass Ah*Bh.
static constexpr int TAH = 0;
static constexpr int TAL = 8192;
static constexpr int TBH = 16384;
static constexpr int TBL = 24576;
static constexpr int STAGE = 32768;
static constexpr int NSTAGE = 3;
static constexpr int SMEM_TOTAL = NSTAGE * STAGE;  // 98304

template<bool SCALE_COL, bool BIAS, bool VSPLIT, bool HALF_OUT>
__global__ void __launch_bounds__(256, 2)
mma_gemm_kernel(const __half* __restrict__ Ah_, const __half* __restrict__ Al_,
                long long aBatch,
                const __half* __restrict__ Bh_, const __half* __restrict__ Bl_,
                long long bBatch,
                void* __restrict__ Cv, long long cBatch,
                int K, int nChunks,
                const float* __restrict__ colscale,
                const float* __restrict__ bias,
                __half* __restrict__ vHi, __half* __restrict__ vLo) {
    extern __shared__ char smem[];
    const uint32_t smem_u = smem_to_u32(smem);
    const int tid = threadIdx.x;
    const int lane = tid & 31, wid = tid >> 5;
    const int wm = wid & 3, wn = wid >> 2;
    const int m0 = blockIdx.x * 128, n0 = blockIdx.y * 128, b = blockIdx.z;
    // q,k rows: pure fp16, 1 pass (error attenuated ~4x by norm+softmax chain)
    const bool onePass = VSPLIT && (blockIdx.x < 4);

    const char* Ah = (const char*)(Ah_ + (long long)b * aBatch);
    const char* Al = (const char*)(Al_ + (long long)b * aBatch);
    const char* Bh = (const char*)(Bh_ + (long long)b * bBatch);
    const char* Bl = (const char*)(Bl_ + (long long)b * bBatch);

    const int row0 = tid >> 2;
    const int chunk = tid & 3;
    const long long aoffA = ((long long)(m0 + row0) * K) * 2 + chunk * 16;
    const long long aoffB = ((long long)(m0 + row0 + 64) * K) * 2 + chunk * 16;
    const long long boffA = ((long long)(n0 + row0) * K) * 2 + chunk * 16;
    const long long boffB = ((long long)(n0 + row0 + 64) * K) * 2 + chunk * 16;
    const char* pa0 = Ah + aoffA;  const char* pa1 = Ah + aoffB;
    const char* pl0 = Al + aoffA;  const char* pl1 = Al + aoffB;
    const char* pb0 = Bh + boffA;  const char* pb1 = Bh + boffB;
    const char* pc0 = Bl + boffA;  const char* pc1 = Bl + boffB;
    const int s0 = swz(row0, chunk), s1 = swz(row0 + 64, chunk);

    float acc[2][8][4];
    #pragma unroll
    for (int i = 0; i < 2; i++)
        #pragma unroll
        for (int j = 0; j < 8; j++)
            #pragma unroll
            for (int q = 0; q < 4; q++) acc[i][j][q] = 0.f;

    auto issue = [&](int c) {
        uint32_t d = smem_u + (c % 3) * STAGE;
        long long ko = (long long)c * 64;
        CP_ASYNC16(d + TAH + s0, pa0 + ko);
        CP_ASYNC16(d + TAH + s1, pa1 + ko);
        CP_ASYNC16(d + TBH + s0, pb0 + ko);
        CP_ASYNC16(d + TBH + s1, pb1 + ko);
        if (!onePass) {
            CP_ASYNC16(d + TAL + s0, pl0 + ko);
            CP_ASYNC16(d + TAL + s1, pl1 + ko);
            CP_ASYNC16(d + TBL + s0, pc0 + ko);
            CP_ASYNC16(d + TBL + s1, pc1 + ko);
        }
        CP_COMMIT();
    };
    issue(0); issue(1);

    const int a_r = wm * 32 + (lane & 15);
    const int a_ci = lane >> 4;
    const int b_r = wn * 64 + (lane & 7) + ((lane >> 4) << 3);
    const int b_ci = (lane >> 3) & 1;

    for (int c = 0; c < nChunks; c++) {
        CP_WAIT1();
        __syncthreads();
        if (c + 2 < nChunks) issue(c + 2); else CP_COMMIT();
        const uint32_t sb = smem_u + (c % 3) * STAGE;
        #pragma unroll
        for (int kk = 0; kk < 2; kk++) {
            uint32_t a_hi[2][4], a_lo[2][4], bf[4][4];
            #pragma unroll
            for (int mt = 0; mt < 2; mt++) {
                int r = a_r + mt * 16;
                uint32_t ar = sb + TAH + swz(r, kk * 2 + a_ci);
                ldsm4(a_hi[mt], ar);
                if (!onePass) ldsm4(a_lo[mt], ar + (TAL - TAH));
            }
            #pragma unroll
            for (int p = 0; p < 4; p++) {
                int r = b_r + p * 16;
                ldsm4(bf[p], sb + TBH + swz(r, kk * 2 + b_ci));
            }
            #pragma unroll
            for (int mt = 0; mt < 2; mt++)
                #pragma unroll
                for (int p = 0; p < 4; p++) {
                    mma16816(acc[mt][2 * p],     a_hi[mt], &bf[p][0]);
                    mma16816(acc[mt][2 * p + 1], a_hi[mt], &bf[p][2]);
                    if (!onePass) {
                        mma16816(acc[mt][2 * p],     a_lo[mt], &bf[p][0]);
                        mma16816(acc[mt][2 * p + 1], a_lo[mt], &bf[p][2]);
                    }
                }
            if (!onePass) {
                #pragma unroll
                for (int p = 0; p < 4; p++) {
                    int r = b_r + p * 16;
                    ldsm4(bf[p], sb + TBL + swz(r, kk * 2 + b_ci));
                }
                #pragma unroll
                for (int mt = 0; mt < 2; mt++)
                    #pragma unroll
                    for (int p = 0; p < 4; p++) {
                        mma16816(acc[mt][2 * p],     a_hi[mt], &bf[p][0]);
                        mma16816(acc[mt][2 * p + 1], a_hi[mt], &bf[p][2]);
                    }
            }
        }
    }
    CP_WAIT0();
    __syncthreads();

    float cs0[8], cs1[8];
    #pragma unroll
    for (int nt = 0; nt < 8; nt++) {
        if (SCALE_COL) {
            int col = wn * 64 + nt * 8 + (lane & 3) * 2;
            float2 cv = *(const float2*)(colscale + (long long)b * GN + n0 + col);
            cs0[nt] = cv.x; cs1[nt] = cv.y;
        } else { cs0[nt] = 1.f; cs1[nt] = 1.f; }
    }

    if (VSPLIT && blockIdx.x >= 4) {
        // v rows: transpose via smem, emit fp16 hi/lo K-major (token, chan)
        float* st = (float*)smem;   // 128 x 128, stride 129
        const int rl = wm * 32 + (lane >> 2);
        #pragma unroll
        for (int mt = 0; mt < 2; mt++) {
            #pragma unroll
            for (int nt = 0; nt < 8; nt++) {
                int col = wn * 64 + nt * 8 + (lane & 3) * 2;
                float* a = acc[mt][nt];
                int r0 = rl + mt * 16, r1 = r0 + 8;
                st[r0 * 129 + col] = a[0] * cs0[nt];
                st[r0 * 129 + col + 1] = a[1] * cs1[nt];
                st[r1 * 129 + col] = a[2] * cs0[nt];
                st[r1 * 129 + col + 1] = a[3] * cs1[nt];
            }
        }
        __syncthreads();
        int n = tid >> 1, half = tid & 1;
        int vc0 = (m0 - 512) + half * 64;
        __half* hdst = vHi + ((long long)b * GN + n0 + n) * GDINNER + vc0;
        __half* ldst = vLo + ((long long)b * GN + n0 + n) * GDINNER + vc0;
        #pragma unroll 8
        for (int j = 0; j < 64; j += 2) {
            __half2 pl;
            __half2 ph = split_hi(st[(half * 64 + j) * 129 + n],
                                  st[(half * 64 + j + 1) * 129 + n], pl);
            *reinterpret_cast<__half2*>(hdst + j) = ph;
            *reinterpret_cast<__half2*>(ldst + j) = pl;
        }
        return;
    }

    const int rbase = m0 + wm * 32 + (lane >> 2);
    #pragma unroll
    for (int mt = 0; mt < 2; mt++) {
        int r0 = rbase + mt * 16;
        int r1 = r0 + 8;
        float bv0 = 0.f, bv1 = 0.f;
        if (BIAS) { bv0 = bias[r0]; bv1 = bias[r1]; }
        if (HALF_OUT) {
            __half* c0row = (__half*)Cv + (long long)b * cBatch + (long long)r0 * GN + n0;
            __half* c1row = (__half*)Cv + (long long)b * cBatch + (long long)r1 * GN + n0;
            #pragma unroll
            for (int nt = 0; nt < 8; nt++) {
                int col = wn * 64 + nt * 8 + (lane & 3) * 2;
                float* a = acc[mt][nt];
                *(__half2*)(c0row + col) =
                    __halves2half2(__float2half_rn(a[0] * cs0[nt]), __float2half_rn(a[1] * cs1[nt]));
                *(__half2*)(c1row + col) =
                    __halves2half2(__float2half_rn(a[2] * cs0[nt]), __float2half_rn(a[3] * cs1[nt]));
            }
        } else {
            float* c0row = (float*)Cv + (long long)b * cBatch + (long long)r0 * GN + n0;
            float* c1row = (float*)Cv + (long long)b * cBatch + (long long)r1 * GN + n0;
            #pragma unroll
            for (int nt = 0; nt < 8; nt++) {
                int col = wn * 64 + nt * 8 + (lane & 3) * 2;
                float* a = acc[mt][nt];
                *(float2*)(c0row + col) = make_float2(a[0] * cs0[nt] + bv0, a[1] * cs1[nt] + bv0);
                *(float2*)(c1row + col) = make_float2(a[2] * cs0[nt] + bv1, a[3] * cs1[nt] + bv1);
            }
        }
    }
}

// ---------------- gram partials + channel norm partials (fp16 reads) -------
__global__ void __launch_bounds__(256) gram_kernel() {
    int p = blockIdx.x, h = blockIdx.y, b = blockIdx.z;
    __shared__ float qs[32 * 129];
    __shared__ float ks[32 * 129];
    int tid = threadIdx.x;
    int g = tid >> 6;
    int r = tid & 63;
    int i0 = (r >> 3) * 4;
    int j0 = (r & 7) * 4;
    float acc[4][4] = {};
    float nacc = 0.f;
    const int nch = tid & 63, nq = tid >> 6;
    const __half* qbase = g_QK + ((long long)b * 512 + h * 32) * GN + p * 1024;
    const __half* kbase = qbase + (long long)256 * GN;
    int lrow = tid >> 3;
    int lcol = (tid & 7) * 16;
    for (int t = 0; t < 8; t++) {
        long long nn0 = t * 128;
        __syncthreads();
        const __half* qr = qbase + (long long)lrow * GN + nn0 + lcol;
        const __half* kr = kbase + (long long)lrow * GN + nn0 + lcol;
        uint4 qu0 = *(const uint4*)(qr); uint4 qu1 = *(const uint4*)(qr + 8);
        uint4 ku0 = *(const uint4*)(kr); uint4 ku1 = *(const uint4*)(kr + 8);
        float* qd = qs + lrow * 129 + lcol;
        float* kd = ks + lrow * 129 + lcol;
        #pragma unroll
        for (int i = 0; i < 4; i++) {
            float2 f = __half22float2(((const __half2*)&qu0)[i]);
            qd[2 * i] = f.x; qd[2 * i + 1] = f.y;
            f = __half22float2(((const __half2*)&qu1)[i]);
            qd[8 + 2 * i] = f.x; qd[9 + 2 * i] = f.y;
            f = __half22float2(((const __half2*)&ku0)[i]);
            kd[2 * i] = f.x; kd[2 * i + 1] = f.y;
            f = __half22float2(((const __half2*)&ku1)[i]);
            kd[8 + 2 * i] = f.x; kd[9 + 2 * i] = f.y;
        }
        __syncthreads();
        #pragma unroll 8
        for (int s = 0; s < 32; s++) {
            int nn = g * 32 + s;
            float qv[4], kv[4];
            #pragma unroll
            for (int a = 0; a < 4; a++) qv[a] = qs[(i0 + a) * 129 + nn];
            #pragma unroll
            for (int a = 0; a < 4; a++) kv[a] = ks[(j0 + a) * 129 + nn];
            #pragma unroll
            for (int a = 0; a < 4; a++)
                #pragma unroll
                for (int cc = 0; cc < 4; cc++)
                    acc[a][cc] = fmaf(qv[a], kv[cc], acc[a][cc]);
        }
        const float* src = (nch < 32) ? (qs + nch * 129) : (ks + (nch - 32) * 129);
        #pragma unroll 8
        for (int i = 0; i < 32; i++) {
            float v = src[nq * 32 + i];
            nacc = fmaf(v, v, nacc);
        }
    }
    __syncthreads();
    float* red = qs;
    #pragma unroll
    for (int a = 0; a < 4; a++)
        #pragma unroll
        for (int cc = 0; cc < 4; cc++)
            red[g * 1024 + (i0 + a) * 32 + (j0 + cc)] = acc[a][cc];
    ks[tid] = nacc;
    __syncthreads();
    for (int idx = tid; idx < 1024; idx += 256) {
        float sgm = red[idx] + red[1024 + idx] + red[2048 + idx] + red[3072 + idx];
        g_Gpart[(((long long)p * BATCH + b) * GHEADS + h) * 1024 + idx] = sgm;
    }
    if (tid < 64)
        g_Npart[(((long long)p * BATCH + b) * GHEADS + h) * 64 + tid] =
            ks[tid] + ks[64 + tid] + ks[128 + tid] + ks[192 + tid];
}

// ---------------- softmax + W2T = (attn-fold w_out), fp16 split ------------
__global__ void attn_w2_kernel(const float* __restrict__ temp,
                               const float* __restrict__ w_out) {
    int h = blockIdx.x, b = blockIdx.y;
    __shared__ float Asm[1024];
    __shared__ float sinv[64];
    int tid = threadIdx.x;
    float tsc = 8.0f * expf(temp[h]);
    if (tid < 64) {
        float s = 0.f;
        #pragma unroll
        for (int p = 0; p < 8; p++)
            s += g_Npart[(((long long)p * BATCH + b) * GHEADS + h) * 64 + tid];
        sinv[tid] = 1.f / fmaxf(sqrtf(s), 1e-12f);
    }
    __syncthreads();
    for (int idx = tid; idx < 1024; idx += 256) {
        float s = 0.f;
        #pragma unroll
        for (int p = 0; p < 8; p++)
            s += g_Gpart[(((long long)p * BATCH + b) * GHEADS + h) * 1024 + idx];
        int i = idx >> 5, j = idx & 31;
        s *= tsc * sinv[i] * sinv[32 + j];
        Asm[idx] = s;
    }
    __syncthreads();
    int w = tid >> 5, lane = tid & 31;
    for (int t = 0; t < 4; t++) {
        int i = w + t * 8;
        float v = Asm[i * 32 + lane];
        float mx = v;
        for (int off = 16; off; off >>= 1) mx = fmaxf(mx, __shfl_xor_sync(~0u, mx, off));
        float e = expf(v - mx);
        float sm = e;
        for (int off = 16; off; off >>= 1) sm += __shfl_xor_sync(~0u, sm, off);
        Asm[i * 32 + lane] = e / sm;
    }
    __syncthreads();
    for (int idx = tid; idx < 32 * 512; idx += 256) {
        int j = idx & 31, c2 = idx >> 5;
        float s = 0.f;
        #pragma unroll
        for (int i = 0; i < 32; i++)
            s = fmaf(Asm[i * 32 + j], w_out[(h * 32 + i) * 512 + c2], s);
        long long o = ((long long)b * GDIM + c2) * GDINNER + h * 32 + j;
        __half hh = __float2half_rn(s);
        g_W2T_hi[o] = hh;
        g_W2T_lo[o] = __float2half_rn(s - __half2float(hh));
    }
}

// ---------------- launch ----------------------------------------------------
extern "C" void kernel_launch(void* const* d_in, const int* in_sizes, int n_in,
                              void* d_out, int out_size) {
    const float* x      = (const float*)d_in[0];
    const float* gamma  = (const float*)d_in[2];
    const float* w_qkv  = (const float*)d_in[3];
    const float* temp   = (const float*)d_in[4];
    const float* w_out  = (const float*)d_in[5];
    const float* b_out  = (const float*)d_in[6];
    float* y = (float*)d_out;

    float* pInv;
    __half *pQK, *pWgh, *pWgl, *pXh, *pXl, *pVh, *pVl, *pW2h, *pW2l;
    cudaGetSymbolAddress((void**)&pInv, g_invnorm);
    cudaGetSymbolAddress((void**)&pQK,  g_QK);
    cudaGetSymbolAddress((void**)&pWgh, g_WgT_hi);
    cudaGetSymbolAddress((void**)&pWgl, g_WgT_lo);
    cudaGetSymbolAddress((void**)&pXh,  g_xT_hi);
    cudaGetSymbolAddress((void**)&pXl,  g_xT_lo);
    cudaGetSymbolAddress((void**)&pVh,  g_vT_hi);
    cudaGetSymbolAddress((void**)&pVl,  g_vT_lo);
    cudaGetSymbolAddress((void**)&pW2h, g_W2T_hi);
    cudaGetSymbolAddress((void**)&pW2l, g_W2T_lo);

    cudaFuncSetAttribute(mma_gemm_kernel<true, false, true, true>,
                         cudaFuncAttributeMaxDynamicSharedMemorySize, SMEM_TOTAL);
    cudaFuncSetAttribute(mma_gemm_kernel<false, true, false, false>,
                         cudaFuncAttributeMaxDynamicSharedMemorySize, SMEM_TOTAL);

    prep_wg_kernel<<<(GDIM * GM1) / 256, 256>>>(w_qkv, gamma);
    transpose_split_kernel<<<dim3(GN / 64, GDIM / 64, BATCH), 256>>>(x);
    invnorm_reduce_kernel<<<dim3(GN / 256, BATCH), 256>>>();

    // QKV: q,k rows (1-pass fp16) -> g_QK; v rows (3-pass) -> vT fp16 hi/lo
    mma_gemm_kernel<true, false, true, true><<<dim3(GM1 / 128, GN / 128, BATCH), 256, SMEM_TOTAL>>>(
        pWgh, pWgl, 0LL,
        pXh, pXl, (long long)GN * GDIM,
        pQK, (long long)512 * GN,
        GDIM, GDIM / 32, pInv, nullptr, pVh, pVl);

    gram_kernel<<<dim3(8, GHEADS, BATCH), 256>>>();
    attn_w2_kernel<<<dim3(GHEADS, BATCH), 256>>>(temp, w_out);

    // y[b] (512 x 8192) = W2T[b] (512x256) @ vT[b]^T + b_out  (3-pass)
    mma_gemm_kernel<false, true, false, false><<<dim3(GDIM / 128, GN / 128, BATCH), 256, SMEM_TOTAL>>>(
        pW2h, pW2l, (long long)GDIM * GDINNER,
        pVh, pVl, (long long)GN * GDINNER,
        y, (long long)GDIM * GN,
        GDINNER, GDINNER / 32, nullptr, b_out, nullptr, nullptr);
}

// round 14
// speedup vs baseline: 2.0720x; 1.2123x over previous
#include <cuda_runtime.h>
#include <cuda_fp16.h>
#include <math.h>
#include <cstdint>

#define BATCH 8
#define GN 8192
#define GDIM 512
#define GHEADS 8
#define GM1 768
#define GDINNER 256

// ---------------- scratch ---------------------------------------------------
__device__ __align__(128) __half g_WgT_hi[GM1 * GDIM];
__device__ __align__(128) __half g_WgT_lo[GM1 * GDIM];
__device__ __align__(128) __half g_xT_hi[(long long)BATCH * GN * GDIM];
__device__ __align__(128) __half g_xT_lo[(long long)BATCH * GN * GDIM];
__device__ __align__(128) __half g_vT_hi[(long long)BATCH * GN * GDINNER];
__device__ __align__(128) __half g_W2T_hi[BATCH * GDIM * GDINNER];
__device__ __align__(128) __half g_W2T_lo[BATCH * GDIM * GDINNER];
__device__ __align__(128) __half g_QK[(long long)BATCH * 512 * GN];   // q,k fp16
__device__ float g_xnp[8 * BATCH * GN];
__device__ float g_invnorm[BATCH * GN];
__device__ float g_Gpart[8 * BATCH * GHEADS * 32 * 32];
__device__ float g_Npart[8 * BATCH * GHEADS * 64];

// ---------------- helpers ---------------------------------------------------
__device__ __forceinline__ uint32_t smem_to_u32(const void* p) {
    uint32_t a;
    asm("{ .reg .u64 t; cvta.to.shared.u64 t, %1; cvt.u32.u64 %0, t; }" : "=r"(a) : "l"(p));
    return a;
}
__device__ __forceinline__ void ldsm4(uint32_t* r, uint32_t addr) {
    asm volatile("ldmatrix.sync.aligned.m8n8.x4.shared.b16 {%0,%1,%2,%3}, [%4];"
                 : "=r"(r[0]), "=r"(r[1]), "=r"(r[2]), "=r"(r[3]) : "r"(addr));
}
__device__ __forceinline__ void mma16816(float* d, const uint32_t* a, const uint32_t* b) {
    asm volatile("mma.sync.aligned.m16n8k16.row.col.f32.f16.f16.f32 "
                 "{%0,%1,%2,%3}, {%4,%5,%6,%7}, {%8,%9}, {%0,%1,%2,%3};"
                 : "+f"(d[0]), "+f"(d[1]), "+f"(d[2]), "+f"(d[3])
                 : "r"(a[0]), "r"(a[1]), "r"(a[2]), "r"(a[3]), "r"(b[0]), "r"(b[1]));
}
#define CP_ASYNC16(dst, src) \
    asm volatile("cp.async.cg.shared.global [%0], [%1], 16;" :: "r"(dst), "l"(src))
#define CP_COMMIT() asm volatile("cp.async.commit_group;")
#define CP_WAIT1()  asm volatile("cp.async.wait_group 1;")
#define CP_WAIT0()  asm volatile("cp.async.wait_group 0;")

__device__ __forceinline__ int swz(int row, int ci) {
    return row * 64 + ((ci ^ ((row >> 1) & 3)) << 4);
}
__device__ __forceinline__ __half2 split_hi(float v0, float v1, __half2& lo) {
    __half h0 = __float2half_rn(v0), h1 = __float2half_rn(v1);
    lo = __halves2half2(__float2half_rn(v0 - __half2float(h0)),
                        __float2half_rn(v1 - __half2float(h1)));
    return __halves2half2(h0, h1);
}

// ---------------- kernel 0: fold gamma*sqrt(dim) into W, split -------------
__global__ void prep_wg_kernel(const float* __restrict__ w_qkv,
                               const float* __restrict__ gamma) {
    int idx = blockIdx.x * 256 + threadIdx.x;   // over 768*512; out [m][d]
    int m = idx >> 9, d = idx & 511;
    float v = w_qkv[d * GM1 + m] * gamma[d] * 22.627416997969522f;
    __half h = __float2half_rn(v);
    g_WgT_hi[idx] = h;
    g_WgT_lo[idx] = __float2half_rn(v - __half2float(h));
}

// ---------------- transpose + split x (fp16), + partial token norms --------
__global__ void transpose_split_kernel(const float* __restrict__ src) {
    __shared__ float t[64][65];
    __shared__ float nr[256];
    int n0 = blockIdx.x * 64, d0 = blockIdx.y * 64, b = blockIdx.z;
    int tid = threadIdx.x;
    int c = tid & 63, r4 = tid >> 6;
    const float* sb = src + ((long long)b * GDIM + d0) * GN + n0;
    #pragma unroll
    for (int i = 0; i < 16; i++) {
        int row = r4 + i * 4;
        t[row][c] = sb[(long long)row * GN + c];
    }
    __syncthreads();
    int d2 = (tid & 31) * 2, rw = tid >> 5;
    __half* hb = g_xT_hi + ((long long)b * GN + n0) * GDIM + d0;
    __half* lb = g_xT_lo + ((long long)b * GN + n0) * GDIM + d0;
    #pragma unroll
    for (int i = 0; i < 8; i++) {
        int nrow = rw + i * 8;
        __half2 pl;
        __half2 ph = split_hi(t[d2][nrow], t[d2 + 1][nrow], pl);
        *reinterpret_cast<__half2*>(hb + (long long)nrow * GDIM + d2) = ph;
        *reinterpret_cast<__half2*>(lb + (long long)nrow * GDIM + d2) = pl;
    }
    // partial token norms over these 64 dims
    int tok = tid & 63, part = tid >> 6;
    float s = 0.f;
    #pragma unroll
    for (int i = 0; i < 16; i++) {
        float v = t[part * 16 + i][tok];
        s = fmaf(v, v, s);
    }
    nr[tid] = s;
    __syncthreads();
    if (tid < 64)
        g_xnp[((long long)(d0 >> 6) * BATCH + b) * GN + n0 + tid] =
            nr[tid] + nr[64 + tid] + nr[128 + tid] + nr[192 + tid];
}

// ---------------- reduce partial token norms -> invnorm --------------------
__global__ void invnorm_reduce_kernel() {
    int b = blockIdx.y;
    int t = blockIdx.x * 256 + threadIdx.x;
    float s = 0.f;
    #pragma unroll
    for (int d = 0; d < 8; d++)
        s += g_xnp[((long long)d * BATCH + b) * GN + t];
    g_invnorm[b * GN + t] = 1.f / fmaxf(sqrtf(s), 1e-12f);
}

// ---------------- HMMA fp16 GEMM (cp.async 3-stage, 2 CTA/SM) --------------
// C[b](MxGN) = A(MxK) @ B[b](GNxK)^T, tile 128Mx128Nx32K, 256 thr (4x2 warps).
// Non-QK path: D = Ah*Bh + Al*Bh (+ Ah*Bl if BL_PASS).
// QK blocks (VSPLIT && bx<4): pure fp16 1-pass, 64-K chunks (all 4 tile slots).
static constexpr int TAH = 0;
static constexpr int TAL = 8192;
static constexpr int TBH = 16384;
static constexpr int TBL = 24576;
static constexpr int STAGE = 32768;
static constexpr int NSTAGE = 3;
static constexpr int SMEM_TOTAL = NSTAGE * STAGE;  // 98304

template<bool SCALE_COL, bool BIAS, bool VSPLIT, bool HALF_OUT, bool BL_PASS>
__global__ void __launch_bounds__(256, 2)
mma_gemm_kernel(const __half* __restrict__ Ah_, const __half* __restrict__ Al_,
                long long aBatch,
                const __half* __restrict__ Bh_, const __half* __restrict__ Bl_,
                long long bBatch,
                void* __restrict__ Cv, long long cBatch,
                int K, int nChunks,
                const float* __restrict__ colscale,
                const float* __restrict__ bias,
                __half* __restrict__ vHi) {
    extern __shared__ char smem[];
    const uint32_t smem_u = smem_to_u32(smem);
    const int tid = threadIdx.x;
    const int lane = tid & 31, wid = tid >> 5;
    const int wm = wid & 3, wn = wid >> 2;
    const int m0 = blockIdx.x * 128, n0 = blockIdx.y * 128, b = blockIdx.z;
    const bool qkMode = VSPLIT && (blockIdx.x < 4);

    const char* Ah = (const char*)(Ah_ + (long long)b * aBatch);
    const char* Al = (const char*)(Al_ + (long long)b * aBatch);
    const char* Bh = (const char*)(Bh_ + (long long)b * bBatch);
    const char* Bl = (const char*)(Bl_ + (long long)b * bBatch);

    const int row0 = tid >> 2;
    const int chunk = tid & 3;
    const long long aoffA = ((long long)(m0 + row0) * K) * 2 + chunk * 16;
    const long long aoffB = ((long long)(m0 + row0 + 64) * K) * 2 + chunk * 16;
    const long long boffA = ((long long)(n0 + row0) * K) * 2 + chunk * 16;
    const long long boffB = ((long long)(n0 + row0 + 64) * K) * 2 + chunk * 16;
    const char* pa0 = Ah + aoffA;  const char* pa1 = Ah + aoffB;
    const char* pl0 = Al + aoffA;  const char* pl1 = Al + aoffB;
    const char* pb0 = Bh + boffA;  const char* pb1 = Bh + boffB;
    const char* pc0 = Bl + boffA;  const char* pc1 = Bl + boffB;
    const int s0 = swz(row0, chunk), s1 = swz(row0 + 64, chunk);

    float acc[2][8][4];
    #pragma unroll
    for (int i = 0; i < 2; i++)
        #pragma unroll
        for (int j = 0; j < 8; j++)
            #pragma unroll
            for (int q = 0; q < 4; q++) acc[i][j][q] = 0.f;

    const int a_r = wm * 32 + (lane & 15);
    const int a_ci = lane >> 4;
    const int b_r = wn * 64 + (lane & 7) + ((lane >> 4) << 3);
    const int b_ci = (lane >> 3) & 1;

    if (qkMode) {
        // ---- 1-pass, 64-K chunks: A k..k+32 -> TAH, k+32..k+64 -> TAL; B likewise ----
        const int nC = nChunks >> 1;
        auto issueQ = [&](int c) {
            uint32_t d = smem_u + (c % 3) * STAGE;
            long long ko = (long long)c * 128;
            CP_ASYNC16(d + TAH + s0, pa0 + ko);
            CP_ASYNC16(d + TAH + s1, pa1 + ko);
            CP_ASYNC16(d + TAL + s0, pa0 + ko + 64);
            CP_ASYNC16(d + TAL + s1, pa1 + ko + 64);
            CP_ASYNC16(d + TBH + s0, pb0 + ko);
            CP_ASYNC16(d + TBH + s1, pb1 + ko);
            CP_ASYNC16(d + TBL + s0, pb0 + ko + 64);
            CP_ASYNC16(d + TBL + s1, pb1 + ko + 64);
            CP_COMMIT();
        };
        issueQ(0); issueQ(1);
        for (int c = 0; c < nC; c++) {
            CP_WAIT1();
            __syncthreads();
            if (c + 2 < nC) issueQ(c + 2); else CP_COMMIT();
            const uint32_t sb = smem_u + (c % 3) * STAGE;
            #pragma unroll
            for (int kk2 = 0; kk2 < 4; kk2++) {
                const int tA = (kk2 < 2) ? TAH : TAL;
                const int tB = (kk2 < 2) ? TBH : TBL;
                const int kk = kk2 & 1;
                uint32_t a_hi[2][4], bf[4][4];
                #pragma unroll
                for (int mt = 0; mt < 2; mt++)
                    ldsm4(a_hi[mt], sb + tA + swz(a_r + mt * 16, kk * 2 + a_ci));
                #pragma unroll
                for (int p = 0; p < 4; p++)
                    ldsm4(bf[p], sb + tB + swz(b_r + p * 16, kk * 2 + b_ci));
                #pragma unroll
                for (int mt = 0; mt < 2; mt++)
                    #pragma unroll
                    for (int p = 0; p < 4; p++) {
                        mma16816(acc[mt][2 * p],     a_hi[mt], &bf[p][0]);
                        mma16816(acc[mt][2 * p + 1], a_hi[mt], &bf[p][2]);
                    }
            }
        }
    } else {
        // ---- 2/3-pass, 32-K chunks ----
        auto issue = [&](int c) {
            uint32_t d = smem_u + (c % 3) * STAGE;
            long long ko = (long long)c * 64;
            CP_ASYNC16(d + TAH + s0, pa0 + ko);
            CP_ASYNC16(d + TAH + s1, pa1 + ko);
            CP_ASYNC16(d + TAL + s0, pl0 + ko);
            CP_ASYNC16(d + TAL + s1, pl1 + ko);
            CP_ASYNC16(d + TBH + s0, pb0 + ko);
            CP_ASYNC16(d + TBH + s1, pb1 + ko);
            if (BL_PASS) {
                CP_ASYNC16(d + TBL + s0, pc0 + ko);
                CP_ASYNC16(d + TBL + s1, pc1 + ko);
            }
            CP_COMMIT();
        };
        issue(0); issue(1);
        for (int c = 0; c < nChunks; c++) {
            CP_WAIT1();
            __syncthreads();
            if (c + 2 < nChunks) issue(c + 2); else CP_COMMIT();
            const uint32_t sb = smem_u + (c % 3) * STAGE;
            #pragma unroll
            for (int kk = 0; kk < 2; kk++) {
                uint32_t a_hi[2][4], a_lo[2][4], bf[4][4];
                #pragma unroll
                for (int mt = 0; mt < 2; mt++) {
                    uint32_t ar = sb + TAH + swz(a_r + mt * 16, kk * 2 + a_ci);
                    ldsm4(a_hi[mt], ar);
                    ldsm4(a_lo[mt], ar + (TAL - TAH));
                }
                #pragma unroll
                for (int p = 0; p < 4; p++)
                    ldsm4(bf[p], sb + TBH + swz(b_r + p * 16, kk * 2 + b_ci));
                #pragma unroll
                for (int mt = 0; mt < 2; mt++)
                    #pragma unroll
                    for (int p = 0; p < 4; p++) {
                        mma16816(acc[mt][2 * p],     a_hi[mt], &bf[p][0]);
                        mma16816(acc[mt][2 * p + 1], a_hi[mt], &bf[p][2]);
                        mma16816(acc[mt][2 * p],     a_lo[mt], &bf[p][0]);
                        mma16816(acc[mt][2 * p + 1], a_lo[mt], &bf[p][2]);
                    }
                if (BL_PASS) {
                    #pragma unroll
                    for (int p = 0; p < 4; p++)
                        ldsm4(bf[p], sb + TBL + swz(b_r + p * 16, kk * 2 + b_ci));
                    #pragma unroll
                    for (int mt = 0; mt < 2; mt++)
                        #pragma unroll
                        for (int p = 0; p < 4; p++) {
                            mma16816(acc[mt][2 * p],     a_hi[mt], &bf[p][0]);
                            mma16816(acc[mt][2 * p + 1], a_hi[mt], &bf[p][2]);
                        }
                }
            }
        }
    }
    CP_WAIT0();
    __syncthreads();

    float cs0[8], cs1[8];
    #pragma unroll
    for (int nt = 0; nt < 8; nt++) {
        if (SCALE_COL) {
            int col = wn * 64 + nt * 8 + (lane & 3) * 2;
            float2 cv = *(const float2*)(colscale + (long long)b * GN + n0 + col);
            cs0[nt] = cv.x; cs1[nt] = cv.y;
        } else { cs0[nt] = 1.f; cs1[nt] = 1.f; }
    }

    if (VSPLIT && blockIdx.x >= 4) {
        // v rows: transpose via smem, emit fp16 K-major (token, chan); hi only
        float* st = (float*)smem;   // 128 x 128, stride 129
        const int rl = wm * 32 + (lane >> 2);
        #pragma unroll
        for (int mt = 0; mt < 2; mt++) {
            #pragma unroll
            for (int nt = 0; nt < 8; nt++) {
                int col = wn * 64 + nt * 8 + (lane & 3) * 2;
                float* a = acc[mt][nt];
                int r0 = rl + mt * 16, r1 = r0 + 8;
                st[r0 * 129 + col] = a[0] * cs0[nt];
                st[r0 * 129 + col + 1] = a[1] * cs1[nt];
                st[r1 * 129 + col] = a[2] * cs0[nt];
                st[r1 * 129 + col + 1] = a[3] * cs1[nt];
            }
        }
        __syncthreads();
        int n = tid >> 1, half = tid & 1;
        int vc0 = (m0 - 512) + half * 64;
        __half* hdst = vHi + ((long long)b * GN + n0 + n) * GDINNER + vc0;
        #pragma unroll 8
        for (int j = 0; j < 64; j += 2) {
            float v0 = st[(half * 64 + j) * 129 + n];
            float v1 = st[(half * 64 + j + 1) * 129 + n];
            *reinterpret_cast<__half2*>(hdst + j) =
                __halves2half2(__float2half_rn(v0), __float2half_rn(v1));
        }
        return;
    }

    const int rbase = m0 + wm * 32 + (lane >> 2);
    #pragma unroll
    for (int mt = 0; mt < 2; mt++) {
        int r0 = rbase + mt * 16;
        int r1 = r0 + 8;
        float bv0 = 0.f, bv1 = 0.f;
        if (BIAS) { bv0 = bias[r0]; bv1 = bias[r1]; }
        if (HALF_OUT) {
            __half* c0row = (__half*)Cv + (long long)b * cBatch + (long long)r0 * GN + n0;
            __half* c1row = (__half*)Cv + (long long)b * cBatch + (long long)r1 * GN + n0;
            #pragma unroll
            for (int nt = 0; nt < 8; nt++) {
                int col = wn * 64 + nt * 8 + (lane & 3) * 2;
                float* a = acc[mt][nt];
                *(__half2*)(c0row + col) =
                    __halves2half2(__float2half_rn(a[0] * cs0[nt]), __float2half_rn(a[1] * cs1[nt]));
                *(__half2*)(c1row + col) =
                    __halves2half2(__float2half_rn(a[2] * cs0[nt]), __float2half_rn(a[3] * cs1[nt]));
            }
        } else {
            float* c0row = (float*)Cv + (long long)b * cBatch + (long long)r0 * GN + n0;
            float* c1row = (float*)Cv + (long long)b * cBatch + (long long)r1 * GN + n0;
            #pragma unroll
            for (int nt = 0; nt < 8; nt++) {
                int col = wn * 64 + nt * 8 + (lane & 3) * 2;
                float* a = acc[mt][nt];
                *(float2*)(c0row + col) = make_float2(a[0] * cs0[nt] + bv0, a[1] * cs1[nt] + bv0);
                *(float2*)(c1row + col) = make_float2(a[2] * cs0[nt] + bv1, a[3] * cs1[nt] + bv1);
            }
        }
    }
}

// ---------------- gram partials + channel norm partials (fp16 reads) -------
__global__ void __launch_bounds__(256) gram_kernel() {
    int p = blockIdx.x, h = blockIdx.y, b = blockIdx.z;
    __shared__ float qs[32 * 129];
    __shared__ float ks[32 * 129];
    int tid = threadIdx.x;
    int g = tid >> 6;
    int r = tid & 63;
    int i0 = (r >> 3) * 4;
    int j0 = (r & 7) * 4;
    float acc[4][4] = {};
    float nacc = 0.f;
    const int nch = tid & 63, nq = tid >> 6;
    const __half* qbase = g_QK + ((long long)b * 512 + h * 32) * GN + p * 1024;
    const __half* kbase = qbase + (long long)256 * GN;
    int lrow = tid >> 3;
    int lcol = (tid & 7) * 16;
    for (int t = 0; t < 8; t++) {
        long long nn0 = t * 128;
        __syncthreads();
        const __half* qr = qbase + (long long)lrow * GN + nn0 + lcol;
        const __half* kr = kbase + (long long)lrow * GN + nn0 + lcol;
        uint4 qu0 = *(const uint4*)(qr); uint4 qu1 = *(const uint4*)(qr + 8);
        uint4 ku0 = *(const uint4*)(kr); uint4 ku1 = *(const uint4*)(kr + 8);
        float* qd = qs + lrow * 129 + lcol;
        float* kd = ks + lrow * 129 + lcol;
        #pragma unroll
        for (int i = 0; i < 4; i++) {
            float2 f = __half22float2(((const __half2*)&qu0)[i]);
            qd[2 * i] = f.x; qd[2 * i + 1] = f.y;
            f = __half22float2(((const __half2*)&qu1)[i]);
            qd[8 + 2 * i] = f.x; qd[9 + 2 * i] = f.y;
            f = __half22float2(((const __half2*)&ku0)[i]);
            kd[2 * i] = f.x; kd[2 * i + 1] = f.y;
            f = __half22float2(((const __half2*)&ku1)[i]);
            kd[8 + 2 * i] = f.x; kd[9 + 2 * i] = f.y;
        }
        __syncthreads();
        #pragma unroll 8
        for (int s = 0; s < 32; s++) {
            int nn = g * 32 + s;
            float qv[4], kv[4];
            #pragma unroll
            for (int a = 0; a < 4; a++) qv[a] = qs[(i0 + a) * 129 + nn];
            #pragma unroll
            for (int a = 0; a < 4; a++) kv[a] = ks[(j0 + a) * 129 + nn];
            #pragma unroll
            for (int a = 0; a < 4; a++)
                #pragma unroll
                for (int cc = 0; cc < 4; cc++)
                    acc[a][cc] = fmaf(qv[a], kv[cc], acc[a][cc]);
        }
        const float* src = (nch < 32) ? (qs + nch * 129) : (ks + (nch - 32) * 129);
        #pragma unroll 8
        for (int i = 0; i < 32; i++) {
            float v = src[nq * 32 + i];
            nacc = fmaf(v, v, nacc);
        }
    }
    __syncthreads();
    float* red = qs;
    #pragma unroll
    for (int a = 0; a < 4; a++)
        #pragma unroll
        for (int cc = 0; cc < 4; cc++)
            red[g * 1024 + (i0 + a) * 32 + (j0 + cc)] = acc[a][cc];
    ks[tid] = nacc;
    __syncthreads();
    for (int idx = tid; idx < 1024; idx += 256) {
        float sgm = red[idx] + red[1024 + idx] + red[2048 + idx] + red[3072 + idx];
        g_Gpart[(((long long)p * BATCH + b) * GHEADS + h) * 1024 + idx] = sgm;
    }
    if (tid < 64)
        g_Npart[(((long long)p * BATCH + b) * GHEADS + h) * 64 + tid] =
            ks[tid] + ks[64 + tid] + ks[128 + tid] + ks[192 + tid];
}

// ---------------- softmax + W2T = (attn-fold w_out), fp16 split ------------
__global__ void attn_w2_kernel(const float* __restrict__ temp,
                               const float* __restrict__ w_out) {
    int h = blockIdx.x, b = blockIdx.y;
    __shared__ float Asm[1024];
    __shared__ float sinv[64];
    int tid = threadIdx.x;
    float tsc = 8.0f * expf(temp[h]);
    if (tid < 64) {
        float s = 0.f;
        #pragma unroll
        for (int p = 0; p < 8; p++)
            s += g_Npart[(((long long)p * BATCH + b) * GHEADS + h) * 64 + tid];
        sinv[tid] = 1.f / fmaxf(sqrtf(s), 1e-12f);
    }
    __syncthreads();
    for (int idx = tid; idx < 1024; idx += 256) {
        float s = 0.f;
        #pragma unroll
        for (int p = 0; p < 8; p++)
            s += g_Gpart[(((long long)p * BATCH + b) * GHEADS + h) * 1024 + idx];
        int i = idx >> 5, j = idx & 31;
        s *= tsc * sinv[i] * sinv[32 + j];
        Asm[idx] = s;
    }
    __syncthreads();
    int w = tid >> 5, lane = tid & 31;
    for (int t = 0; t < 4; t++) {
        int i = w + t * 8;
        float v = Asm[i * 32 + lane];
        float mx = v;
        for (int off = 16; off; off >>= 1) mx = fmaxf(mx, __shfl_xor_sync(~0u, mx, off));
        float e = expf(v - mx);
        float sm = e;
        for (int off = 16; off; off >>= 1) sm += __shfl_xor_sync(~0u, sm, off);
        Asm[i * 32 + lane] = e / sm;
    }
    __syncthreads();
    for (int idx = tid; idx < 32 * 512; idx += 256) {
        int j = idx & 31, c2 = idx >> 5;
        float s = 0.f;
        #pragma unroll
        for (int i = 0; i < 32; i++)
            s = fmaf(Asm[i * 32 + j], w_out[(h * 32 + i) * 512 + c2], s);
        long long o = ((long long)b * GDIM + c2) * GDINNER + h * 32 + j;
        __half hh = __float2half_rn(s);
        g_W2T_hi[o] = hh;
        g_W2T_lo[o] = __float2half_rn(s - __half2float(hh));
    }
}

// ---------------- launch ----------------------------------------------------
extern "C" void kernel_launch(void* const* d_in, const int* in_sizes, int n_in,
                              void* d_out, int out_size) {
    const float* x      = (const float*)d_in[0];
    const float* gamma  = (const float*)d_in[2];
    const float* w_qkv  = (const float*)d_in[3];
    const float* temp   = (const float*)d_in[4];
    const float* w_out  = (const float*)d_in[5];
    const float* b_out  = (const float*)d_in[6];
    float* y = (float*)d_out;

    float* pInv;
    __half *pQK, *pWgh, *pWgl, *pXh, *pXl, *pVh, *pW2h, *pW2l;
    cudaGetSymbolAddress((void**)&pInv, g_invnorm);
    cudaGetSymbolAddress((void**)&pQK,  g_QK);
    cudaGetSymbolAddress((void**)&pWgh, g_WgT_hi);
    cudaGetSymbolAddress((void**)&pWgl, g_WgT_lo);
    cudaGetSymbolAddress((void**)&pXh,  g_xT_hi);
    cudaGetSymbolAddress((void**)&pXl,  g_xT_lo);
    cudaGetSymbolAddress((void**)&pVh,  g_vT_hi);
    cudaGetSymbolAddress((void**)&pW2h, g_W2T_hi);
    cudaGetSymbolAddress((void**)&pW2l, g_W2T_lo);

    cudaFuncSetAttribute(mma_gemm_kernel<true, false, true, true, true>,
                         cudaFuncAttributeMaxDynamicSharedMemorySize, SMEM_TOTAL);
    cudaFuncSetAttribute(mma_gemm_kernel<false, true, false, false, false>,
                         cudaFuncAttributeMaxDynamicSharedMemorySize, SMEM_TOTAL);

    prep_wg_kernel<<<(GDIM * GM1) / 256, 256>>>(w_qkv, gamma);
    transpose_split_kernel<<<dim3(GN / 64, GDIM / 64, BATCH), 256>>>(x);
    invnorm_reduce_kernel<<<dim3(GN / 256, BATCH), 256>>>();

    // QKV: q,k rows (1-pass fp16, 64-K chunks) -> g_QK; v rows (3-pass) -> vT hi
    mma_gemm_kernel<true, false, true, true, true>
        <<<dim3(GM1 / 128, GN / 128, BATCH), 256, SMEM_TOTAL>>>(
        pWgh, pWgl, 0LL,
        pXh, pXl, (long long)GN * GDIM,
        pQK, (long long)512 * GN,
        GDIM, GDIM / 32, pInv, nullptr, pVh);

    gram_kernel<<<dim3(8, GHEADS, BATCH), 256>>>();
    attn_w2_kernel<<<dim3(GHEADS, BATCH), 256>>>(temp, w_out);

    // y[b] = W2T[b]^T @ vT[b]^T + b_out  (2-pass: Ah*Bh + Al*Bh)
    mma_gemm_kernel<false, true, false, false, false>
        <<<dim3(GDIM / 128, GN / 128, BATCH), 256, SMEM_TOTAL>>>(
        pW2h, pW2l, (long long)GDIM * GDINNER,
        pVh, pVh, (long long)GN * GDINNER,
        y, (long long)GDIM * GN,
        GDINNER, GDINNER / 32, nullptr, b_out, nullptr);
}

// round 15
// speedup vs baseline: 2.3047x; 1.1123x over previous
#include <cuda_runtime.h>
#include <cuda_fp16.h>
#include <math.h>
#include <cstdint>

#define BATCH 8
#define GN 8192
#define GDIM 512
#define GHEADS 8
#define GM1 768
#define GDINNER 256

// ---------------- scratch ---------------------------------------------------
__device__ __align__(128) __half g_WgT_hi[GM1 * GDIM];
__device__ __align__(128) __half g_WgT_lo[GM1 * GDIM];
__device__ __align__(128) __half g_xT_hi[(long long)BATCH * GN * GDIM];
__device__ __align__(128) __half g_vT_hi[(long long)BATCH * GN * GDINNER];
__device__ __align__(128) __half g_W2T_hi[BATCH * GDIM * GDINNER];
__device__ __align__(128) __half g_W2T_lo[BATCH * GDIM * GDINNER];
__device__ __align__(128) __half g_QK[(long long)BATCH * 512 * GN];   // q,k fp16
__device__ float g_xnp[8 * BATCH * GN];
__device__ float g_invnorm[BATCH * GN];
__device__ float g_Gpart[8 * BATCH * GHEADS * 32 * 32];
__device__ float g_Npart[8 * BATCH * GHEADS * 64];

// ---------------- helpers ---------------------------------------------------
__device__ __forceinline__ uint32_t smem_to_u32(const void* p) {
    uint32_t a;
    asm("{ .reg .u64 t; cvta.to.shared.u64 t, %1; cvt.u32.u64 %0, t; }" : "=r"(a) : "l"(p));
    return a;
}
__device__ __forceinline__ void ldsm4(uint32_t* r, uint32_t addr) {
    asm volatile("ldmatrix.sync.aligned.m8n8.x4.shared.b16 {%0,%1,%2,%3}, [%4];"
                 : "=r"(r[0]), "=r"(r[1]), "=r"(r[2]), "=r"(r[3]) : "r"(addr));
}
__device__ __forceinline__ void mma16816(float* d, const uint32_t* a, const uint32_t* b) {
    asm volatile("mma.sync.aligned.m16n8k16.row.col.f32.f16.f16.f32 "
                 "{%0,%1,%2,%3}, {%4,%5,%6,%7}, {%8,%9}, {%0,%1,%2,%3};"
                 : "+f"(d[0]), "+f"(d[1]), "+f"(d[2]), "+f"(d[3])
                 : "r"(a[0]), "r"(a[1]), "r"(a[2]), "r"(a[3]), "r"(b[0]), "r"(b[1]));
}
#define CP_ASYNC16(dst, src) \
    asm volatile("cp.async.cg.shared.global [%0], [%1], 16;" :: "r"(dst), "l"(src))
#define CP_COMMIT() asm volatile("cp.async.commit_group;")
#define CP_WAIT1()  asm volatile("cp.async.wait_group 1;")
#define CP_WAIT0()  asm volatile("cp.async.wait_group 0;")

__device__ __forceinline__ int swz(int row, int ci) {
    return row * 64 + ((ci ^ ((row >> 1) & 3)) << 4);
}

// ---------------- kernel 0: fold gamma*sqrt(dim) into W, split -------------
__global__ void prep_wg_kernel(const float* __restrict__ w_qkv,
                               const float* __restrict__ gamma) {
    int idx = blockIdx.x * 256 + threadIdx.x;   // over 768*512; out [m][d]
    int m = idx >> 9, d = idx & 511;
    float v = w_qkv[d * GM1 + m] * gamma[d] * 22.627416997969522f;
    __half h = __float2half_rn(v);
    g_WgT_hi[idx] = h;
    g_WgT_lo[idx] = __float2half_rn(v - __half2float(h));
}

// ---------------- transpose x -> fp16 hi only, + partial token norms -------
__global__ void transpose_split_kernel(const float* __restrict__ src) {
    __shared__ float t[64][65];
    __shared__ float nr[256];
    int n0 = blockIdx.x * 64, d0 = blockIdx.y * 64, b = blockIdx.z;
    int tid = threadIdx.x;
    int c = tid & 63, r4 = tid >> 6;
    const float* sb = src + ((long long)b * GDIM + d0) * GN + n0;
    #pragma unroll
    for (int i = 0; i < 16; i++) {
        int row = r4 + i * 4;
        t[row][c] = sb[(long long)row * GN + c];
    }
    __syncthreads();
    int d2 = (tid & 31) * 2, rw = tid >> 5;
    __half* hb = g_xT_hi + ((long long)b * GN + n0) * GDIM + d0;
    #pragma unroll
    for (int i = 0; i < 8; i++) {
        int nrow = rw + i * 8;
        *reinterpret_cast<__half2*>(hb + (long long)nrow * GDIM + d2) =
            __halves2half2(__float2half_rn(t[d2][nrow]), __float2half_rn(t[d2 + 1][nrow]));
    }
    // partial token norms over these 64 dims
    int tok = tid & 63, part = tid >> 6;
    float s = 0.f;
    #pragma unroll
    for (int i = 0; i < 16; i++) {
        float v = t[part * 16 + i][tok];
        s = fmaf(v, v, s);
    }
    nr[tid] = s;
    __syncthreads();
    if (tid < 64)
        g_xnp[((long long)(d0 >> 6) * BATCH + b) * GN + n0 + tid] =
            nr[tid] + nr[64 + tid] + nr[128 + tid] + nr[192 + tid];
}

// ---------------- reduce partial token norms -> invnorm --------------------
__global__ void invnorm_reduce_kernel() {
    int b = blockIdx.y;
    int t = blockIdx.x * 256 + threadIdx.x;
    float s = 0.f;
    #pragma unroll
    for (int d = 0; d < 8; d++)
        s += g_xnp[((long long)d * BATCH + b) * GN + t];
    g_invnorm[b * GN + t] = 1.f / fmaxf(sqrtf(s), 1e-12f);
}

// ---------------- HMMA fp16 GEMM (cp.async 3-stage, 2 CTA/SM) --------------
// C[b](MxGN) = A(MxK) @ B[b](GNxK)^T, tile 128Mx128Nx32K, 256 thr (4x2 warps).
// Non-QK path: D = Ah*Bh + Al*Bh (+ Ah*Bl if BL_PASS).
// QK blocks (VSPLIT && bx<4): pure fp16 1-pass, 64-K chunks (all 4 tile slots).
static constexpr int TAH = 0;
static constexpr int TAL = 8192;
static constexpr int TBH = 16384;
static constexpr int TBL = 24576;
static constexpr int STAGE = 32768;
static constexpr int NSTAGE = 3;
static constexpr int SMEM_TOTAL = NSTAGE * STAGE;  // 98304

template<bool SCALE_COL, bool BIAS, bool VSPLIT, bool HALF_OUT, bool BL_PASS>
__global__ void __launch_bounds__(256, 2)
mma_gemm_kernel(const __half* __restrict__ Ah_, const __half* __restrict__ Al_,
                long long aBatch,
                const __half* __restrict__ Bh_, const __half* __restrict__ Bl_,
                long long bBatch,
                void* __restrict__ Cv, long long cBatch,
                int K, int nChunks,
                const float* __restrict__ colscale,
                const float* __restrict__ bias,
                __half* __restrict__ vHi) {
    extern __shared__ char smem[];
    const uint32_t smem_u = smem_to_u32(smem);
    const int tid = threadIdx.x;
    const int lane = tid & 31, wid = tid >> 5;
    const int wm = wid & 3, wn = wid >> 2;
    const int m0 = blockIdx.x * 128, n0 = blockIdx.y * 128, b = blockIdx.z;
    const bool qkMode = VSPLIT && (blockIdx.x < 4);

    const char* Ah = (const char*)(Ah_ + (long long)b * aBatch);
    const char* Al = (const char*)(Al_ + (long long)b * aBatch);
    const char* Bh = (const char*)(Bh_ + (long long)b * bBatch);
    const char* Bl = (const char*)(Bl_ + (long long)b * bBatch);

    const int row0 = tid >> 2;
    const int chunk = tid & 3;
    const long long aoffA = ((long long)(m0 + row0) * K) * 2 + chunk * 16;
    const long long aoffB = ((long long)(m0 + row0 + 64) * K) * 2 + chunk * 16;
    const long long boffA = ((long long)(n0 + row0) * K) * 2 + chunk * 16;
    const long long boffB = ((long long)(n0 + row0 + 64) * K) * 2 + chunk * 16;
    const char* pa0 = Ah + aoffA;  const char* pa1 = Ah + aoffB;
    const char* pl0 = Al + aoffA;  const char* pl1 = Al + aoffB;
    const char* pb0 = Bh + boffA;  const char* pb1 = Bh + boffB;
    const char* pc0 = Bl + boffA;  const char* pc1 = Bl + boffB;
    const int s0 = swz(row0, chunk), s1 = swz(row0 + 64, chunk);

    float acc[2][8][4];
    #pragma unroll
    for (int i = 0; i < 2; i++)
        #pragma unroll
        for (int j = 0; j < 8; j++)
            #pragma unroll
            for (int q = 0; q < 4; q++) acc[i][j][q] = 0.f;

    const int a_r = wm * 32 + (lane & 15);
    const int a_ci = lane >> 4;
    const int b_r = wn * 64 + (lane & 7) + ((lane >> 4) << 3);
    const int b_ci = (lane >> 3) & 1;

    if (qkMode) {
        // ---- 1-pass, 64-K chunks ----
        const int nC = nChunks >> 1;
        auto issueQ = [&](int c) {
            uint32_t d = smem_u + (c % 3) * STAGE;
            long long ko = (long long)c * 128;
            CP_ASYNC16(d + TAH + s0, pa0 + ko);
            CP_ASYNC16(d + TAH + s1, pa1 + ko);
            CP_ASYNC16(d + TAL + s0, pa0 + ko + 64);
            CP_ASYNC16(d + TAL + s1, pa1 + ko + 64);
            CP_ASYNC16(d + TBH + s0, pb0 + ko);
            CP_ASYNC16(d + TBH + s1, pb1 + ko);
            CP_ASYNC16(d + TBL + s0, pb0 + ko + 64);
            CP_ASYNC16(d + TBL + s1, pb1 + ko + 64);
            CP_COMMIT();
        };
        issueQ(0); issueQ(1);
        for (int c = 0; c < nC; c++) {
            CP_WAIT1();
            __syncthreads();
            if (c + 2 < nC) issueQ(c + 2); else CP_COMMIT();
            const uint32_t sb = smem_u + (c % 3) * STAGE;
            #pragma unroll
            for (int kk2 = 0; kk2 < 4; kk2++) {
                const int tA = (kk2 < 2) ? TAH : TAL;
                const int tB = (kk2 < 2) ? TBH : TBL;
                const int kk = kk2 & 1;
                uint32_t a_hi[2][4], bf[4][4];
                #pragma unroll
                for (int mt = 0; mt < 2; mt++)
                    ldsm4(a_hi[mt], sb + tA + swz(a_r + mt * 16, kk * 2 + a_ci));
                #pragma unroll
                for (int p = 0; p < 4; p++)
                    ldsm4(bf[p], sb + tB + swz(b_r + p * 16, kk * 2 + b_ci));
                #pragma unroll
                for (int mt = 0; mt < 2; mt++)
                    #pragma unroll
                    for (int p = 0; p < 4; p++) {
                        mma16816(acc[mt][2 * p],     a_hi[mt], &bf[p][0]);
                        mma16816(acc[mt][2 * p + 1], a_hi[mt], &bf[p][2]);
                    }
            }
        }
    } else {
        // ---- 2/3-pass, 32-K chunks ----
        auto issue = [&](int c) {
            uint32_t d = smem_u + (c % 3) * STAGE;
            long long ko = (long long)c * 64;
            CP_ASYNC16(d + TAH + s0, pa0 + ko);
            CP_ASYNC16(d + TAH + s1, pa1 + ko);
            CP_ASYNC16(d + TAL + s0, pl0 + ko);
            CP_ASYNC16(d + TAL + s1, pl1 + ko);
            CP_ASYNC16(d + TBH + s0, pb0 + ko);
            CP_ASYNC16(d + TBH + s1, pb1 + ko);
            if (BL_PASS) {
                CP_ASYNC16(d + TBL + s0, pc0 + ko);
                CP_ASYNC16(d + TBL + s1, pc1 + ko);
            }
            CP_COMMIT();
        };
        issue(0); issue(1);
        for (int c = 0; c < nChunks; c++) {
            CP_WAIT1();
            __syncthreads();
            if (c + 2 < nChunks) issue(c + 2); else CP_COMMIT();
            const uint32_t sb = smem_u + (c % 3) * STAGE;
            #pragma unroll
            for (int kk = 0; kk < 2; kk++) {
                uint32_t a_hi[2][4], a_lo[2][4], bf[4][4];
                #pragma unroll
                for (int mt = 0; mt < 2; mt++) {
                    uint32_t ar = sb + TAH + swz(a_r + mt * 16, kk * 2 + a_ci);
                    ldsm4(a_hi[mt], ar);
                    ldsm4(a_lo[mt], ar + (TAL - TAH));
                }
                #pragma unroll
                for (int p = 0; p < 4; p++)
                    ldsm4(bf[p], sb + TBH + swz(b_r + p * 16, kk * 2 + b_ci));
                #pragma unroll
                for (int mt = 0; mt < 2; mt++)
                    #pragma unroll
                    for (int p = 0; p < 4; p++) {
                        mma16816(acc[mt][2 * p],     a_hi[mt], &bf[p][0]);
                        mma16816(acc[mt][2 * p + 1], a_hi[mt], &bf[p][2]);
                        mma16816(acc[mt][2 * p],     a_lo[mt], &bf[p][0]);
                        mma16816(acc[mt][2 * p + 1], a_lo[mt], &bf[p][2]);
                    }
                if (BL_PASS) {
                    #pragma unroll
                    for (int p = 0; p < 4; p++)
                        ldsm4(bf[p], sb + TBL + swz(b_r + p * 16, kk * 2 + b_ci));
                    #pragma unroll
                    for (int mt = 0; mt < 2; mt++)
                        #pragma unroll
                        for (int p = 0; p < 4; p++) {
                            mma16816(acc[mt][2 * p],     a_hi[mt], &bf[p][0]);
                            mma16816(acc[mt][2 * p + 1], a_hi[mt], &bf[p][2]);
                        }
                }
            }
        }
    }
    CP_WAIT0();
    __syncthreads();

    float cs0[8], cs1[8];
    #pragma unroll
    for (int nt = 0; nt < 8; nt++) {
        if (SCALE_COL) {
            int col = wn * 64 + nt * 8 + (lane & 3) * 2;
            float2 cv = *(const float2*)(colscale + (long long)b * GN + n0 + col);
            cs0[nt] = cv.x; cs1[nt] = cv.y;
        } else { cs0[nt] = 1.f; cs1[nt] = 1.f; }
    }

    if (VSPLIT && blockIdx.x >= 4) {
        // v rows: transpose via smem, emit fp16 K-major (token, chan); hi only
        float* st = (float*)smem;   // 128 x 128, stride 129
        const int rl = wm * 32 + (lane >> 2);
        #pragma unroll
        for (int mt = 0; mt < 2; mt++) {
            #pragma unroll
            for (int nt = 0; nt < 8; nt++) {
                int col = wn * 64 + nt * 8 + (lane & 3) * 2;
                float* a = acc[mt][nt];
                int r0 = rl + mt * 16, r1 = r0 + 8;
                st[r0 * 129 + col] = a[0] * cs0[nt];
                st[r0 * 129 + col + 1] = a[1] * cs1[nt];
                st[r1 * 129 + col] = a[2] * cs0[nt];
                st[r1 * 129 + col + 1] = a[3] * cs1[nt];
            }
        }
        __syncthreads();
        int n = tid >> 1, half = tid & 1;
        int vc0 = (m0 - 512) + half * 64;
        __half* hdst = vHi + ((long long)b * GN + n0 + n) * GDINNER + vc0;
        #pragma unroll 8
        for (int j = 0; j < 64; j += 2) {
            float v0 = st[(half * 64 + j) * 129 + n];
            float v1 = st[(half * 64 + j + 1) * 129 + n];
            *reinterpret_cast<__half2*>(hdst + j) =
                __halves2half2(__float2half_rn(v0), __float2half_rn(v1));
        }
        return;
    }

    const int rbase = m0 + wm * 32 + (lane >> 2);
    #pragma unroll
    for (int mt = 0; mt < 2; mt++) {
        int r0 = rbase + mt * 16;
        int r1 = r0 + 8;
        float bv0 = 0.f, bv1 = 0.f;
        if (BIAS) { bv0 = bias[r0]; bv1 = bias[r1]; }
        if (HALF_OUT) {
            __half* c0row = (__half*)Cv + (long long)b * cBatch + (long long)r0 * GN + n0;
            __half* c1row = (__half*)Cv + (long long)b * cBatch + (long long)r1 * GN + n0;
            #pragma unroll
            for (int nt = 0; nt < 8; nt++) {
                int col = wn * 64 + nt * 8 + (lane & 3) * 2;
                float* a = acc[mt][nt];
                *(__half2*)(c0row + col) =
                    __halves2half2(__float2half_rn(a[0] * cs0[nt]), __float2half_rn(a[1] * cs1[nt]));
                *(__half2*)(c1row + col) =
                    __halves2half2(__float2half_rn(a[2] * cs0[nt]), __float2half_rn(a[3] * cs1[nt]));
            }
        } else {
            float* c0row = (float*)Cv + (long long)b * cBatch + (long long)r0 * GN + n0;
            float* c1row = (float*)Cv + (long long)b * cBatch + (long long)r1 * GN + n0;
            #pragma unroll
            for (int nt = 0; nt < 8; nt++) {
                int col = wn * 64 + nt * 8 + (lane & 3) * 2;
                float* a = acc[mt][nt];
                *(float2*)(c0row + col) = make_float2(a[0] * cs0[nt] + bv0, a[1] * cs1[nt] + bv0);
                *(float2*)(c1row + col) = make_float2(a[2] * cs0[nt] + bv1, a[3] * cs1[nt] + bv1);
            }
        }
    }
}

// ---------------- gram partials + channel norm partials (fp16 reads) -------
__global__ void __launch_bounds__(256) gram_kernel() {
    int p = blockIdx.x, h = blockIdx.y, b = blockIdx.z;
    __shared__ float qs[32 * 129];
    __shared__ float ks[32 * 129];
    int tid = threadIdx.x;
    int g = tid >> 6;
    int r = tid & 63;
    int i0 = (r >> 3) * 4;
    int j0 = (r & 7) * 4;
    float acc[4][4] = {};
    float nacc = 0.f;
    const int nch = tid & 63, nq = tid >> 6;
    const __half* qbase = g_QK + ((long long)b * 512 + h * 32) * GN + p * 1024;
    const __half* kbase = qbase + (long long)256 * GN;
    int lrow = tid >> 3;
    int lcol = (tid & 7) * 16;
    for (int t = 0; t < 8; t++) {
        long long nn0 = t * 128;
        __syncthreads();
        const __half* qr = qbase + (long long)lrow * GN + nn0 + lcol;
        const __half* kr = kbase + (long long)lrow * GN + nn0 + lcol;
        uint4 qu0 = *(const uint4*)(qr); uint4 qu1 = *(const uint4*)(qr + 8);
        uint4 ku0 = *(const uint4*)(kr); uint4 ku1 = *(const uint4*)(kr + 8);
        float* qd = qs + lrow * 129 + lcol;
        float* kd = ks + lrow * 129 + lcol;
        #pragma unroll
        for (int i = 0; i < 4; i++) {
            float2 f = __half22float2(((const __half2*)&qu0)[i]);
            qd[2 * i] = f.x; qd[2 * i + 1] = f.y;
            f = __half22float2(((const __half2*)&qu1)[i]);
            qd[8 + 2 * i] = f.x; qd[9 + 2 * i] = f.y;
            f = __half22float2(((const __half2*)&ku0)[i]);
            kd[2 * i] = f.x; kd[2 * i + 1] = f.y;
            f = __half22float2(((const __half2*)&ku1)[i]);
            kd[8 + 2 * i] = f.x; kd[9 + 2 * i] = f.y;
        }
        __syncthreads();
        #pragma unroll 8
        for (int s = 0; s < 32; s++) {
            int nn = g * 32 + s;
            float qv[4], kv[4];
            #pragma unroll
            for (int a = 0; a < 4; a++) qv[a] = qs[(i0 + a) * 129 + nn];
            #pragma unroll
            for (int a = 0; a < 4; a++) kv[a] = ks[(j0 + a) * 129 + nn];
            #pragma unroll
            for (int a = 0; a < 4; a++)
                #pragma unroll
                for (int cc = 0; cc < 4; cc++)
                    acc[a][cc] = fmaf(qv[a], kv[cc], acc[a][cc]);
        }
        const float* src = (nch < 32) ? (qs + nch * 129) : (ks + (nch - 32) * 129);
        #pragma unroll 8
        for (int i = 0; i < 32; i++) {
            float v = src[nq * 32 + i];
            nacc = fmaf(v, v, nacc);
        }
    }
    __syncthreads();
    float* red = qs;
    #pragma unroll
    for (int a = 0; a < 4; a++)
        #pragma unroll
        for (int cc = 0; cc < 4; cc++)
            red[g * 1024 + (i0 + a) * 32 + (j0 + cc)] = acc[a][cc];
    ks[tid] = nacc;
    __syncthreads();
    for (int idx = tid; idx < 1024; idx += 256) {
        float sgm = red[idx] + red[1024 + idx] + red[2048 + idx] + red[3072 + idx];
        g_Gpart[(((long long)p * BATCH + b) * GHEADS + h) * 1024 + idx] = sgm;
    }
    if (tid < 64)
        g_Npart[(((long long)p * BATCH + b) * GHEADS + h) * 64 + tid] =
            ks[tid] + ks[64 + tid] + ks[128 + tid] + ks[192 + tid];
}

// ---------------- softmax + W2T = (attn-fold w_out), fp16 split ------------
__global__ void attn_w2_kernel(const float* __restrict__ temp,
                               const float* __restrict__ w_out) {
    int h = blockIdx.x, b = blockIdx.y;
    __shared__ float Asm[1024];
    __shared__ float sinv[64];
    int tid = threadIdx.x;
    float tsc = 8.0f * expf(temp[h]);
    if (tid < 64) {
        float s = 0.f;
        #pragma unroll
        for (int p = 0; p < 8; p++)
            s += g_Npart[(((long long)p * BATCH + b) * GHEADS + h) * 64 + tid];
        sinv[tid] = 1.f / fmaxf(sqrtf(s), 1e-12f);
    }
    __syncthreads();
    for (int idx = tid; idx < 1024; idx += 256) {
        float s = 0.f;
        #pragma unroll
        for (int p = 0; p < 8; p++)
            s += g_Gpart[(((long long)p * BATCH + b) * GHEADS + h) * 1024 + idx];
        int i = idx >> 5, j = idx & 31;
        s *= tsc * sinv[i] * sinv[32 + j];
        Asm[idx] = s;
    }
    __syncthreads();
    int w = tid >> 5, lane = tid & 31;
    for (int t = 0; t < 4; t++) {
        int i = w + t * 8;
        float v = Asm[i * 32 + lane];
        float mx = v;
        for (int off = 16; off; off >>= 1) mx = fmaxf(mx, __shfl_xor_sync(~0u, mx, off));
        float e = expf(v - mx);
        float sm = e;
        for (int off = 16; off; off >>= 1) sm += __shfl_xor_sync(~0u, sm, off);
        Asm[i * 32 + lane] = e / sm;
    }
    __syncthreads();
    for (int idx = tid; idx < 32 * 512; idx += 256) {
        int j = idx & 31, c2 = idx >> 5;
        float s = 0.f;
        #pragma unroll
        for (int i = 0; i < 32; i++)
            s = fmaf(Asm[i * 32 + j], w_out[(h * 32 + i) * 512 + c2], s);
        long long o = ((long long)b * GDIM + c2) * GDINNER + h * 32 + j;
        __half hh = __float2half_rn(s);
        g_W2T_hi[o] = hh;
        g_W2T_lo[o] = __float2half_rn(s - __half2float(hh));
    }
}

// ---------------- launch ----------------------------------------------------
extern "C" void kernel_launch(void* const* d_in, const int* in_sizes, int n_in,
                              void* d_out, int out_size) {
    const float* x      = (const float*)d_in[0];
    const float* gamma  = (const float*)d_in[2];
    const float* w_qkv  = (const float*)d_in[3];
    const float* temp   = (const float*)d_in[4];
    const float* w_out  = (const float*)d_in[5];
    const float* b_out  = (const float*)d_in[6];
    float* y = (float*)d_out;

    float* pInv;
    __half *pQK, *pWgh, *pWgl, *pXh, *pVh, *pW2h, *pW2l;
    cudaGetSymbolAddress((void**)&pInv, g_invnorm);
    cudaGetSymbolAddress((void**)&pQK,  g_QK);
    cudaGetSymbolAddress((void**)&pWgh, g_WgT_hi);
    cudaGetSymbolAddress((void**)&pWgl, g_WgT_lo);
    cudaGetSymbolAddress((void**)&pXh,  g_xT_hi);
    cudaGetSymbolAddress((void**)&pVh,  g_vT_hi);
    cudaGetSymbolAddress((void**)&pW2h, g_W2T_hi);
    cudaGetSymbolAddress((void**)&pW2l, g_W2T_lo);

    cudaFuncSetAttribute(mma_gemm_kernel<true, false, true, true, false>,
                         cudaFuncAttributeMaxDynamicSharedMemorySize, SMEM_TOTAL);
    cudaFuncSetAttribute(mma_gemm_kernel<false, true, false, false, false>,
                         cudaFuncAttributeMaxDynamicSharedMemorySize, SMEM_TOTAL);

    prep_wg_kernel<<<(GDIM * GM1) / 256, 256>>>(w_qkv, gamma);
    transpose_split_kernel<<<dim3(GN / 64, GDIM / 64, BATCH), 256>>>(x);
    invnorm_reduce_kernel<<<dim3(GN / 256, BATCH), 256>>>();

    // QKV: q,k rows (1-pass fp16, 64-K chunks) -> g_QK;
    // v rows (2-pass: Wh*x + Wl*x) -> vT fp16 hi
    mma_gemm_kernel<true, false, true, true, false>
        <<<dim3(GM1 / 128, GN / 128, BATCH), 256, SMEM_TOTAL>>>(
        pWgh, pWgl, 0LL,
        pXh, pXh, (long long)GN * GDIM,
        pQK, (long long)512 * GN,
        GDIM, GDIM / 32, pInv, nullptr, pVh);

    gram_kernel<<<dim3(8, GHEADS, BATCH), 256>>>();
    attn_w2_kernel<<<dim3(GHEADS, BATCH), 256>>>(temp, w_out);

    // y[b] = W2T[b]^T @ vT[b]^T + b_out  (2-pass: W2h*v + W2l*v)
    mma_gemm_kernel<false, true, false, false, false>
        <<<dim3(GDIM / 128, GN / 128, BATCH), 256, SMEM_TOTAL>>>(
        pW2h, pW2l, (long long)GDIM * GDINNER,
        pVh, pVh, (long long)GN * GDINNER,
        y, (long long)GDIM * GN,
        GDINNER, GDINNER / 32, nullptr, b_out, nullptr);
}